// round 13
// baseline (speedup 1.0000x reference)
#include <cuda_runtime.h>
#include <cstdint>

#define N_NODES 50000
#define N_EDGES 800000
#define EAUG    (N_EDGES + N_NODES)
#define HID     128
#define NCLS    40

// ---------------- scratch (static device globals; no runtime alloc) --------
__device__ float  d_h0 [N_NODES * HID];
__device__ float  d_x1 [N_NODES * HID];
__device__ float  d_tmp[N_NODES * HID];
__device__ float  d_G  [(size_t)N_NODES * 256];   // [xg | xself]
__device__ float  d_SC [N_NODES * HID];
__device__ float  d_SD [N_NODES * HID];
__device__ float2 d_PQ [N_NODES];
__device__ float2 d_s  [EAUG];                    // {exp(s), exp(1-s)}
__device__ float  d_Z  [2 * N_NODES];
__device__ float  d_stats[2 * HID];
__device__ int    d_off [N_NODES + 1];
__device__ int    d_cur [N_NODES];
__device__ int    d_cnt [N_NODES];
__device__ int    d_eid [EAUG];

// ============================================================================
// Tensor-core GEMM via mma.sync m16n8k16 bf16, 3-term split at staging (R9).
// Optionally zeroes the 256-float bn-stats buffer from block (0,0).
// ============================================================================
struct TJob {
    const float* A;
    const float* B;
    const float* bias;
    float*       C;
    int ldc;
    int coff;
};
struct TJobs { TJob j[2]; };

#define BA_STR 36
#define BB_STR 68
#define BSM_TOTAL ((2*128*BA_STR + 2*128*BB_STR) * 4)   // 106496 B

__device__ __forceinline__ uint32_t prmt_hi(uint32_t a, uint32_t b) {
    uint32_t d;
    asm("prmt.b32 %0, %1, %2, 0x7632;" : "=r"(d) : "r"(a), "r"(b));
    return d;
}
__device__ __forceinline__ uint32_t bf16x2_rn(float lo_e, float hi_e) {
    uint32_t d;
    asm("cvt.rn.bf16x2.f32 %0, %1, %2;" : "=r"(d) : "f"(hi_e), "f"(lo_e));
    return d;
}
__device__ __forceinline__ void split4(float4 v, uint32_t* hw, uint32_t* lw) {
    uint32_t ux = __float_as_uint(v.x), uy = __float_as_uint(v.y);
    uint32_t uz = __float_as_uint(v.z), uw = __float_as_uint(v.w);
    hw[0] = prmt_hi(ux, uy);
    hw[1] = prmt_hi(uz, uw);
    float lx = v.x - __uint_as_float(ux & 0xFFFF0000u);
    float ly = v.y - __uint_as_float(uy & 0xFFFF0000u);
    float lz = v.z - __uint_as_float(uz & 0xFFFF0000u);
    float lw_ = v.w - __uint_as_float(uw & 0xFFFF0000u);
    lw[0] = bf16x2_rn(lx, ly);
    lw[1] = bf16x2_rn(lz, lw_);
}
__device__ __forceinline__ void mma_bf16(float* d, const uint32_t* a,
                                         const uint32_t* b) {
    asm volatile(
        "mma.sync.aligned.m16n8k16.row.col.f32.bf16.bf16.f32 "
        "{%0,%1,%2,%3}, {%4,%5,%6,%7}, {%8,%9}, {%0,%1,%2,%3};"
        : "+f"(d[0]), "+f"(d[1]), "+f"(d[2]), "+f"(d[3])
        : "r"(a[0]), "r"(a[1]), "r"(a[2]), "r"(a[3]), "r"(b[0]), "r"(b[1]));
}

__global__ void __launch_bounds__(256, 2) gemm_tc(TJobs jobs, int nrows,
                                                  float* stats_zero)
{
    extern __shared__ uint32_t smw[];
    uint32_t* Ah = smw;
    uint32_t* Al = smw + 128 * BA_STR;
    uint32_t* Bh = smw + 2 * 128 * BA_STR;
    uint32_t* Bl = Bh + 128 * BB_STR;

    const TJob job = jobs.j[blockIdx.y];
    const int row0 = blockIdx.x * 128;
    const int tid  = threadIdx.x;
    const int wid  = tid >> 5, lane = tid & 31;
    const int wm   = wid >> 1, wn = wid & 1;
    const int g    = lane >> 2, ti = lane & 3;

    if (stats_zero && blockIdx.x == 0 && blockIdx.y == 0)
        stats_zero[tid] = 0.f;

#pragma unroll
    for (int i = 0; i < 16; i++) {
        int lin = tid + i * 256;
        int n   = lin >> 5;
        int kq  = (lin & 31) << 2;
        float4 v = *(const float4*)(job.B + (size_t)n * 128 + kq);
        uint32_t hw[2], lw[2];
        split4(v, hw, lw);
        int base = n * BB_STR + (kq >> 1);
        Bh[base] = hw[0]; Bh[base + 1] = hw[1];
        Bl[base] = lw[0]; Bl[base + 1] = lw[1];
    }

    float acc[2][8][4];
#pragma unroll
    for (int mt = 0; mt < 2; mt++)
#pragma unroll
        for (int nt = 0; nt < 8; nt++)
#pragma unroll
            for (int u = 0; u < 4; u++) acc[mt][nt][u] = 0.f;

    for (int c = 0; c < 2; c++) {
#pragma unroll
        for (int i = 0; i < 8; i++) {
            int lin = tid + i * 256;
            int r   = lin >> 4;
            int kq  = (lin & 15) << 2;
            int grow = row0 + r;
            float4 v = make_float4(0.f, 0.f, 0.f, 0.f);
            if (grow < nrows)
                v = *(const float4*)(job.A + (size_t)grow * 128 + c * 64 + kq);
            uint32_t hw[2], lw[2];
            split4(v, hw, lw);
            int base = r * BA_STR + (kq >> 1);
            Ah[base] = hw[0]; Ah[base + 1] = hw[1];
            Al[base] = lw[0]; Al[base + 1] = lw[1];
        }
        __syncthreads();

#pragma unroll
        for (int s = 0; s < 4; s++) {
            const int k0w = s * 8;
            uint32_t ah[2][4], al[2][4];
#pragma unroll
            for (int mt = 0; mt < 2; mt++) {
                int rb = wm * 32 + mt * 16;
                int i0 = (rb + g)     * BA_STR + k0w + ti;
                int i1 = (rb + g + 8) * BA_STR + k0w + ti;
                ah[mt][0] = Ah[i0];
                ah[mt][1] = Ah[i1];
                ah[mt][2] = Ah[i0 + 4];
                ah[mt][3] = Ah[i1 + 4];
                al[mt][0] = Al[i0];
                al[mt][1] = Al[i1];
                al[mt][2] = Al[i0 + 4];
                al[mt][3] = Al[i1 + 4];
            }
#pragma unroll
            for (int nt = 0; nt < 8; nt++) {
                int n = wn * 64 + nt * 8 + g;
                int b0 = n * BB_STR + c * 32 + k0w + ti;
                uint32_t bh[2], bl[2];
                bh[0] = Bh[b0]; bh[1] = Bh[b0 + 4];
                bl[0] = Bl[b0]; bl[1] = Bl[b0 + 4];
#pragma unroll
                for (int mt = 0; mt < 2; mt++) {
                    mma_bf16(acc[mt][nt], ah[mt], bh);
                    mma_bf16(acc[mt][nt], ah[mt], bl);
                    mma_bf16(acc[mt][nt], al[mt], bh);
                }
            }
        }
        __syncthreads();
    }

#pragma unroll
    for (int mt = 0; mt < 2; mt++) {
#pragma unroll
        for (int h = 0; h < 2; h++) {
            int grow = row0 + wm * 32 + mt * 16 + g + h * 8;
            if (grow >= nrows) continue;
            float* cp = job.C + (size_t)grow * job.ldc + job.coff + wn * 64;
#pragma unroll
            for (int nt = 0; nt < 8; nt++) {
                int col = nt * 8 + 2 * ti;
                float vx = acc[mt][nt][2 * h];
                float vy = acc[mt][nt][2 * h + 1];
                if (job.bias) {
                    vx += job.bias[wn * 64 + col];
                    vy += job.bias[wn * 64 + col + 1];
                }
                *(float2*)(cp + col) = make_float2(vx, vy);
            }
        }
    }
}

// ---------------- scalar GEMM (classifier only, ncols=40) -------------------
struct GemmJob {
    const float* A;
    const float* B;
    const float* bias;
    float*       C;
    int ldc;
    int coff;
    int ncols;
};
struct GemmJobs { GemmJob j[2]; };

__device__ __forceinline__ void fma2(unsigned long long& d,
                                     unsigned long long a, unsigned long long b) {
    asm("fma.rn.f32x2 %0, %1, %2, %0;" : "+l"(d) : "l"(a), "l"(b));
}
__device__ __forceinline__ void unpack2(unsigned long long v, float& lo, float& hi) {
    asm("mov.b64 {%0, %1}, %2;" : "=f"(lo), "=f"(hi) : "l"(v));
}

#define AS_STRIDE 260
#define BS_STRIDE 144

__global__ void __launch_bounds__(256, 2) gemm_nt(
    GemmJobs jobs, int nrows)
{
    const GemmJob job = jobs.j[blockIdx.y];
    const float* __restrict__ A    = job.A;
    const float* __restrict__ B    = job.B;
    const float* __restrict__ bias = job.bias;
    const int ncols = job.ncols;
    const int row0  = blockIdx.x * 128;

    __shared__ float As[16][AS_STRIDE];
    __shared__ float Bs[16][BS_STRIDE];

    const int t  = threadIdx.x;
    const int tx = t & 15;
    const int ty = t >> 4;

    unsigned long long acc[8][4];
#pragma unroll
    for (int y = 0; y < 8; y++)
#pragma unroll
        for (int xp = 0; xp < 4; xp++) acc[y][xp] = 0ULL;

    const int b_base = tx * 8 + ((tx >> 2) << 2);

    for (int k0 = 0; k0 < 128; k0 += 16) {
#pragma unroll
        for (int i = 0; i < 2; i++) {
            int lin = t + i * 256;
            int r   = lin >> 2;
            int kq  = lin & 3;
            float4 v = make_float4(0.f, 0.f, 0.f, 0.f);
            int grow = row0 + r;
            if (grow < nrows)
                v = *(const float4*)(A + (size_t)grow * 128 + k0 + kq * 4);
            *(float2*)&As[kq * 4 + 0][2 * r] = make_float2(v.x, v.x);
            *(float2*)&As[kq * 4 + 1][2 * r] = make_float2(v.y, v.y);
            *(float2*)&As[kq * 4 + 2][2 * r] = make_float2(v.z, v.z);
            *(float2*)&As[kq * 4 + 3][2 * r] = make_float2(v.w, v.w);
        }
#pragma unroll
        for (int i = 0; i < 2; i++) {
            int lin = t + i * 256;
            int j   = lin >> 2;
            int kq  = lin & 3;
            float4 v = make_float4(0.f, 0.f, 0.f, 0.f);
            if (j < ncols)
                v = *(const float4*)(B + (size_t)j * 128 + k0 + kq * 4);
            int pj = j + ((j >> 5) << 2);
            Bs[kq * 4 + 0][pj] = v.x;
            Bs[kq * 4 + 1][pj] = v.y;
            Bs[kq * 4 + 2][pj] = v.z;
            Bs[kq * 4 + 3][pj] = v.w;
        }
        __syncthreads();
#pragma unroll
        for (int kk = 0; kk < 16; kk++) {
            unsigned long long ad[8], bp[4];
            const ulonglong2* ap = (const ulonglong2*)&As[kk][ty * 16];
            const ulonglong2* bq = (const ulonglong2*)&Bs[kk][b_base];
#pragma unroll
            for (int i = 0; i < 4; i++) {
                ulonglong2 u = ap[i];
                ad[2 * i]     = u.x;
                ad[2 * i + 1] = u.y;
            }
#pragma unroll
            for (int i = 0; i < 2; i++) {
                ulonglong2 u = bq[i];
                bp[2 * i]     = u.x;
                bp[2 * i + 1] = u.y;
            }
#pragma unroll
            for (int y = 0; y < 8; y++)
#pragma unroll
                for (int xp = 0; xp < 4; xp++)
                    fma2(acc[y][xp], ad[y], bp[xp]);
        }
        __syncthreads();
    }

#pragma unroll
    for (int y = 0; y < 8; y++) {
        int grow = row0 + ty * 8 + y;
        if (grow >= nrows) continue;
        float* cp = job.C + (size_t)grow * job.ldc + job.coff;
        float c[8];
#pragma unroll
        for (int xp = 0; xp < 4; xp++)
            unpack2(acc[y][xp], c[2 * xp], c[2 * xp + 1]);
#pragma unroll
        for (int xq = 0; xq < 2; xq++) {
            int col = tx * 8 + xq * 4;
            if (col >= ncols) continue;
            float4 v = make_float4(c[xq * 4 + 0], c[xq * 4 + 1],
                                   c[xq * 4 + 2], c[xq * 4 + 3]);
            if (bias) {
                v.x += bias[col + 0];
                v.y += bias[col + 1];
                v.z += bias[col + 2];
                v.w += bias[col + 3];
            }
            *(float4*)(cp + col) = v;
        }
    }
}

// ---------------- BatchNorm --------------------------------------------------
__global__ void bn_stats(const float* __restrict__ X, float* __restrict__ stats)
{
    int c  = threadIdx.x;
    int r0 = blockIdx.x * 64;
    int r1 = min(r0 + 64, N_NODES);
    float s = 0.f, q = 0.f;
    for (int r = r0; r < r1; r++) {
        float v = X[(size_t)r * 128 + c];
        s += v;
        q = fmaf(v, v, q);
    }
    atomicAdd(&stats[c], s);
    atomicAdd(&stats[128 + c], q);
}

__global__ void bn_apply(const float4* __restrict__ X, const float* __restrict__ stats,
                         const float* __restrict__ gamma, const float* __restrict__ beta,
                         const float4* __restrict__ residual, float4* __restrict__ out)
{
    int i = blockIdx.x * blockDim.x + threadIdx.x;
    if (i >= N_NODES * 32) return;
    int c0 = (i & 31) * 4;
    const float invN = 1.f / (float)N_NODES;
    float4 v = X[i];
    float r[4] = {v.x, v.y, v.z, v.w};
#pragma unroll
    for (int k = 0; k < 4; k++) {
        int c = c0 + k;
        float m   = stats[c] * invN;
        float var = stats[128 + c] * invN - m * m;
        float u = gamma[c] * (r[k] - m) * rsqrtf(var + 1e-5f) + beta[c];
        r[k] = fmaxf(u, 0.f);
    }
    float4 o = make_float4(r[0], r[1], r[2], r[3]);
    if (residual) {
        float4 rv = residual[i];
        o.x += rv.x; o.y += rv.y; o.z += rv.z; o.w += rv.w;
    }
    out[i] = o;
}

// ---------------- small utility kernels -------------------------------------
__global__ void recip_f(float* __restrict__ p, int n)
{
    int i = blockIdx.x * blockDim.x + threadIdx.x;
    if (i < n) p[i] = 1.f / p[i];
}

__global__ void init_counts_k(int* __restrict__ cnt)
{
    int i = blockIdx.x * blockDim.x + threadIdx.x;
    if (i < N_NODES) cnt[i] = 1;   // self loop
}

__global__ void hist_k(const int* __restrict__ ei1, int* __restrict__ cnt)
{
    int e = blockIdx.x * blockDim.x + threadIdx.x;
    if (e < N_EDGES) atomicAdd(&cnt[ei1[e]], 1);
}

__global__ void scan_k(const int* __restrict__ cnt, int* __restrict__ off,
                       int* __restrict__ cur)
{
    __shared__ int sh[1024];
    const int CH = (N_NODES + 1023) / 1024;
    int t = threadIdx.x;
    int base = t * CH;
    int local = 0;
    for (int i = 0; i < CH; i++) {
        int idx = base + i;
        if (idx < N_NODES) local += cnt[idx];
    }
    sh[t] = local;
    __syncthreads();
    for (int o = 1; o < 1024; o <<= 1) {
        int v = 0;
        if (t >= o) v = sh[t - o];
        __syncthreads();
        if (t >= o) sh[t] += v;
        __syncthreads();
    }
    int run = (t == 0) ? 0 : sh[t - 1];
    for (int i = 0; i < CH; i++) {
        int idx = base + i;
        if (idx < N_NODES) {
            off[idx] = run;
            cur[idx] = run;
            run += cnt[idx];
        }
    }
    if (t == 0) off[N_NODES] = EAUG;
}

__global__ void csr_fill_k(const int* __restrict__ ei1, int* __restrict__ cur,
                           int* __restrict__ eid)
{
    int e = blockIdx.x * blockDim.x + threadIdx.x;
    if (e >= EAUG) return;
    int c = (e < N_EDGES) ? ei1[e] : (e - N_EDGES);
    int pos = atomicAdd(&cur[c], 1);
    eid[pos] = e;
}

// ---------------- per-node Wh dots (+ zero Z: saves a launch) -----------------
__global__ void pq_kernel(const float* __restrict__ G, const float* __restrict__ Wh,
                          float2* __restrict__ PQ, float* __restrict__ Z)
{
    int node = (blockIdx.x * blockDim.x + threadIdx.x) >> 5;
    int lane = threadIdx.x & 31;
    if (node >= N_NODES) return;
    float4 xg = ((const float4*)(G + (size_t)node * 256))[lane];
    float4 a  = ((const float4*)Wh)[lane];
    float4 b  = ((const float4*)Wh)[lane + 32];
    float p = xg.x * a.x + xg.y * a.y + xg.z * a.z + xg.w * a.w;
    float q = xg.x * b.x + xg.y * b.y + xg.z * b.z + xg.w * b.w;
#pragma unroll
    for (int o = 16; o > 0; o >>= 1) {
        p += __shfl_xor_sync(0xffffffffu, p, o);
        q += __shfl_xor_sync(0xffffffffu, q, o);
    }
    if (lane == 0) {
        PQ[node] = make_float2(p, q);
        Z[node] = 0.f;
        Z[N_NODES + node] = 0.f;
    }
}

// ---------------- edge pass 1 (R9: warp per edge) ------------------------------
__global__ void edge_pass1(const float* __restrict__ G,
                           const int* __restrict__ ei0, const int* __restrict__ ei1,
                           const float2* __restrict__ PQ, const float* __restrict__ bh,
                           float2* __restrict__ s_buf, float* __restrict__ Z)
{
    int gw   = (blockIdx.x * blockDim.x + threadIdx.x) >> 5;
    int lane = threadIdx.x & 31;
    if (gw >= EAUG) return;
    int r, c;
    if (gw < N_EDGES) { r = ei0[gw]; c = ei1[gw]; }
    else              { r = gw - N_EDGES; c = r; }

    float4 xr = ((const float4*)(G + (size_t)r * 256))[lane];
    float4 xc = ((const float4*)(G + (size_t)c * 256))[lane];

    float dx = xr.x - xc.x, dy = xr.y - xc.y, dz = xr.z - xc.z, dw = xr.w - xc.w;
    float ss = dx * dx + dy * dy + dz * dz + dw * dw;
#pragma unroll
    for (int o = 16; o > 0; o >>= 1)
        ss += __shfl_xor_sync(0xffffffffu, ss, o);
    if (lane == 0) {
        float g = sqrtf(ss + 1e-12f);
        float t = PQ[r].x + PQ[c].y + bh[0];
        float h = fmaxf(t, 0.f) + log1pf(__expf(-fabsf(t)));   // softplus
        float s = 1.f / (1.f + __expf(g + h));                 // sigmoid(-(g+h))
        float es = __expf(s);
        float ed = __expf(1.f - s);
        s_buf[gw] = make_float2(es, ed);
        atomicAdd(&Z[r],           es);
        atomicAdd(&Z[N_NODES + r], ed);
    }
}

// ---------------- aggregation (R9 math + index prefetch) ----------------------
__global__ void agg_k(const float* __restrict__ X,
                      const int* __restrict__ off, const int* __restrict__ eid,
                      const int* __restrict__ ei0,
                      const float2* __restrict__ s_buf, const float* __restrict__ invZ,
                      float* __restrict__ SC, float* __restrict__ SD)
{
    int node = (blockIdx.x * blockDim.x + threadIdx.x) >> 5;
    int lane = threadIdx.x & 31;
    if (node >= N_NODES) return;

    int p0 = off[node], p1 = off[node + 1];
    float4 ac = make_float4(0.f, 0.f, 0.f, 0.f);
    float4 ad = make_float4(0.f, 0.f, 0.f, 0.f);

    int e_nxt = eid[p0];
    int r_nxt = (e_nxt < N_EDGES) ? ei0[e_nxt] : (e_nxt - N_EDGES);
    for (int p = p0; p < p1; p++) {
        int e = e_nxt, r = r_nxt;
        if (p + 1 < p1) {
            e_nxt = eid[p + 1];
            r_nxt = (e_nxt < N_EDGES) ? ei0[e_nxt] : (e_nxt - N_EDGES);
        }
        float2 es = s_buf[e];
        float wc = es.x * invZ[r];
        float wd = es.y * invZ[N_NODES + r];
        float4 v = ((const float4*)(X + (size_t)r * 128))[lane];
        ac.x = fmaf(wc, v.x, ac.x); ac.y = fmaf(wc, v.y, ac.y);
        ac.z = fmaf(wc, v.z, ac.z); ac.w = fmaf(wc, v.w, ac.w);
        ad.x = fmaf(wd, v.x, ad.x); ad.y = fmaf(wd, v.y, ad.y);
        ad.z = fmaf(wd, v.z, ad.z); ad.w = fmaf(wd, v.w, ad.w);
    }
    ((float4*)(SC + (size_t)node * 128))[lane] = ac;
    ((float4*)(SD + (size_t)node * 128))[lane] = ad;
}

// ---------------- gate + combine + residual ----------------------------------
__global__ void gate_k(const float* __restrict__ OC, const float* __restrict__ OD,
                       const float* __restrict__ G,
                       const float* __restrict__ Wgate, const float* __restrict__ bgate,
                       const float* __restrict__ residual, float* __restrict__ out)
{
    int node = (blockIdx.x * blockDim.x + threadIdx.x) >> 5;
    int lane = threadIdx.x & 31;
    if (node >= N_NODES) return;

    float4 ac = ((const float4*)(OC + (size_t)node * 128))[lane];
    float4 ad = ((const float4*)(OD + (size_t)node * 128))[lane];
    float4 sf = ((const float4*)(G + (size_t)node * 256 + 128))[lane];

    float l[3];
#pragma unroll
    for (int k = 0; k < 3; k++) {
        float4 w0 = ((const float4*)(Wgate + k * 384))[lane];
        float4 w1 = ((const float4*)(Wgate + k * 384 + 128))[lane];
        float4 w2 = ((const float4*)(Wgate + k * 384 + 256))[lane];
        l[k] = w0.x * ac.x + w0.y * ac.y + w0.z * ac.z + w0.w * ac.w
             + w1.x * ad.x + w1.y * ad.y + w1.z * ad.z + w1.w * ad.w
             + w2.x * sf.x + w2.y * sf.y + w2.z * sf.z + w2.w * sf.w;
    }
#pragma unroll
    for (int o = 16; o > 0; o >>= 1) {
        l[0] += __shfl_xor_sync(0xffffffffu, l[0], o);
        l[1] += __shfl_xor_sync(0xffffffffu, l[1], o);
        l[2] += __shfl_xor_sync(0xffffffffu, l[2], o);
    }
    l[0] += bgate[0]; l[1] += bgate[1]; l[2] += bgate[2];
    float m  = fmaxf(l[0], fmaxf(l[1], l[2]));
    float e0 = __expf(l[0] - m), e1 = __expf(l[1] - m), e2 = __expf(l[2] - m);
    float inv = 1.f / (e0 + e1 + e2);
    float g0 = e0 * inv, g1 = e1 * inv, g2 = e2 * inv;

    float4 o4;
    o4.x = g0 * ac.x + g1 * ad.x + g2 * sf.x;
    o4.y = g0 * ac.y + g1 * ad.y + g2 * sf.y;
    o4.z = g0 * ac.z + g1 * ad.z + g2 * sf.z;
    o4.w = g0 * ac.w + g1 * ad.w + g2 * sf.w;
    if (residual) {
        float4 rv = ((const float4*)(residual + (size_t)node * 128))[lane];
        o4.x += rv.x; o4.y += rv.y; o4.z += rv.z; o4.w += rv.w;
    }
    ((float4*)(out + (size_t)node * 128))[lane] = o4;
}

// ---------------- launch ------------------------------------------------------
extern "C" void kernel_launch(void* const* d_in, const int* in_sizes, int n_in,
                              void* d_out, int out_size)
{
    (void)in_sizes; (void)n_in; (void)out_size;
    const float* x       = (const float*)d_in[0];
    const int*   ei      = (const int*)d_in[1];
    const float* mlp_W   = (const float*)d_in[2];
    const float* mlp_b   = (const float*)d_in[3];
    const float* mlp_g   = (const float*)d_in[4];
    const float* mlp_be  = (const float*)d_in[5];
    const float* bn0_g   = (const float*)d_in[6];
    const float* bn0_be  = (const float*)d_in[7];
    const float* cls_W   = (const float*)d_in[8];
    const float* cls_b   = (const float*)d_in[9];
    const float* Wg[2]    = {(const float*)d_in[10], (const float*)d_in[19]};
    const float* Wh[2]    = {(const float*)d_in[11], (const float*)d_in[20]};
    const float* bh[2]    = {(const float*)d_in[12], (const float*)d_in[21]};
    const float* Wcon[2]  = {(const float*)d_in[13], (const float*)d_in[22]};
    const float* Wdis[2]  = {(const float*)d_in[14], (const float*)d_in[23]};
    const float* Wself[2] = {(const float*)d_in[15], (const float*)d_in[24]};
    const float* bself[2] = {(const float*)d_in[16], (const float*)d_in[25]};
    const float* Wgate[2] = {(const float*)d_in[17], (const float*)d_in[26]};
    const float* bgate[2] = {(const float*)d_in[18], (const float*)d_in[27]};
    const int* ei0 = ei;
    const int* ei1 = ei + N_EDGES;
    float* out = (float*)d_out;

    float *pH0, *pX1, *pTmp, *pG, *pSC, *pSD, *pZ, *pStats;
    float2 *pS, *pPQ;
    int *pOff, *pCur, *pCnt, *pEid;
    cudaGetSymbolAddress((void**)&pH0,   d_h0);
    cudaGetSymbolAddress((void**)&pX1,   d_x1);
    cudaGetSymbolAddress((void**)&pTmp,  d_tmp);
    cudaGetSymbolAddress((void**)&pG,    d_G);
    cudaGetSymbolAddress((void**)&pSC,   d_SC);
    cudaGetSymbolAddress((void**)&pSD,   d_SD);
    cudaGetSymbolAddress((void**)&pPQ,   d_PQ);
    cudaGetSymbolAddress((void**)&pS,    d_s);
    cudaGetSymbolAddress((void**)&pZ,    d_Z);
    cudaGetSymbolAddress((void**)&pStats,d_stats);
    cudaGetSymbolAddress((void**)&pOff,  d_off);
    cudaGetSymbolAddress((void**)&pCur,  d_cur);
    cudaGetSymbolAddress((void**)&pCnt,  d_cnt);
    cudaGetSymbolAddress((void**)&pEid,  d_eid);

    cudaFuncSetAttribute(gemm_tc, cudaFuncAttributeMaxDynamicSharedMemorySize,
                         BSM_TOTAL);

    const int GR = (N_NODES + 127) / 128;          // 391 row blocks
    const int NODE_WARPS = (N_NODES * 32 + 255) / 256;

    // ---- MLP + BN + relu -> h0 (gemm also zeroes bn stats)
    {
        TJobs tj = {};
        tj.j[0] = {x, mlp_W, mlp_b, pTmp, 128, 0};
        tj.j[1] = tj.j[0];
        gemm_tc<<<dim3(GR, 1), 256, BSM_TOTAL>>>(tj, N_NODES, pStats);
    }
    bn_stats<<<(N_NODES + 63) / 64, 128>>>(pTmp, pStats);
    bn_apply<<<NODE_WARPS, 256>>>((const float4*)pTmp, pStats,
                                  mlp_g, mlp_be, nullptr, (float4*)pH0);

    // ---- CSR by col (shared by both layers)
    init_counts_k<<<(N_NODES + 255) / 256, 256>>>(pCnt);
    hist_k<<<(N_EDGES + 255) / 256, 256>>>(ei1, pCnt);
    scan_k<<<1, 1024>>>(pCnt, pOff, pCur);
    csr_fill_k<<<(EAUG + 255) / 256, 256>>>(ei1, pCur, pEid);

    // ---- conv layers
    const float* lin[2] = {pH0, pX1};
    for (int l = 0; l < 2; l++) {
        const float* X = lin[l];
        {   // G = [X@Wg.T | X@Wself.T + bself]
            TJobs tj = {};
            tj.j[0] = {X, Wg[l],    nullptr,  pG, 256, 0};
            tj.j[1] = {X, Wself[l], bself[l], pG, 256, 128};
            gemm_tc<<<dim3(GR, 2), 256, BSM_TOTAL>>>(tj, N_NODES, nullptr);
        }
        pq_kernel<<<NODE_WARPS, 256>>>(pG, Wh[l], pPQ, pZ);
        edge_pass1<<<(EAUG * 32 + 255) / 256, 256>>>(pG, ei0, ei1, pPQ, bh[l],
                                                     pS, pZ);
        recip_f<<<(2 * N_NODES + 255) / 256, 256>>>(pZ, 2 * N_NODES);
        agg_k<<<NODE_WARPS, 256>>>(X, pOff, pEid, ei0, pS, pZ, pSC, pSD);
        {   // SC = SC@Wcon.T, SD = SD@Wdis.T (zeroes bn stats on layer 0)
            TJobs tj = {};
            tj.j[0] = {pSC, Wcon[l], nullptr, pSC, 128, 0};
            tj.j[1] = {pSD, Wdis[l], nullptr, pSD, 128, 0};
            gemm_tc<<<dim3(GR, 2), 256, BSM_TOTAL>>>(tj, N_NODES,
                                                     (l == 0) ? pStats : nullptr);
        }
        gate_k<<<NODE_WARPS, 256>>>(pSC, pSD, pG, Wgate[l], bgate[l],
                                    (l == 0) ? nullptr : pX1, pTmp);
        if (l == 0) {
            bn_stats<<<(N_NODES + 63) / 64, 128>>>(pTmp, pStats);
            bn_apply<<<NODE_WARPS, 256>>>((const float4*)pTmp, pStats,
                                          bn0_g, bn0_be,
                                          (const float4*)pH0, (float4*)pX1);
        }
    }

    // ---- classifier: out = x2 @ cls_W.T + cls_b   (x2 lives in d_tmp)
    {
        GemmJobs gj = {};
        gj.j[0] = {pTmp, cls_W, cls_b, out, 40, 0, 40};
        gj.j[1] = gj.j[0];
        gemm_nt<<<dim3(GR, 1), 256>>>(gj, N_NODES);
    }
}

// round 14
// speedup vs baseline: 1.0648x; 1.0648x over previous
#include <cuda_runtime.h>
#include <cstdint>

#define N_NODES 50000
#define N_EDGES 800000
#define EAUG    (N_EDGES + N_NODES)
#define HID     128
#define NCLS    40

// ---------------- scratch (static device globals; no runtime alloc) --------
__device__ float  d_h0 [N_NODES * HID];
__device__ float  d_x1 [N_NODES * HID];
__device__ float  d_tmp[N_NODES * HID];
__device__ float  d_G  [(size_t)N_NODES * 256];   // [xg | xself]
__device__ float  d_SC [N_NODES * HID];
__device__ float  d_SD [N_NODES * HID];
__device__ float2 d_PQ [N_NODES];
__device__ float2 d_s  [EAUG];                    // {exp(s), exp(1-s)}
__device__ float  d_Z  [2 * N_NODES];
__device__ float  d_stats[2 * HID];
__device__ int    d_off [N_NODES + 1];
__device__ int    d_cur [N_NODES];
__device__ int    d_cnt [N_NODES];
__device__ int    d_eid [EAUG];

// ============================================================================
// Tensor-core GEMM via mma.sync m16n8k16 bf16, 3-term split done at staging:
//   x = hi + lo;  hi = trunc-bf16(x) (top 16 bits, PRMT-packed);
//   lo = rn-bf16(x - hi).  D = Ah*Bh + Ah*Bl + Al*Bh  (lo*lo dropped ~2^-18).
// 128x128 tile, K=128 (A staged per 64-K chunk, B staged once), 8 warps 4x2.
// Smem word-strides % 32 == 4 -> conflict-free 32-bit fragment loads.
// ============================================================================
struct TJob {
    const float* A;
    const float* B;
    const float* bias;
    float*       C;
    int ldc;
    int coff;
};
struct TJobs { TJob j[2]; };

#define BA_STR 36   // uint32 words per A smem row (32 data + 4 pad)
#define BB_STR 68   // uint32 words per B smem row (64 data + 4 pad)
#define BSM_TOTAL ((2*128*BA_STR + 2*128*BB_STR) * 4)   // 106496 bytes

__device__ __forceinline__ uint32_t prmt_hi(uint32_t a, uint32_t b) {
    uint32_t d;
    asm("prmt.b32 %0, %1, %2, 0x7632;" : "=r"(d) : "r"(a), "r"(b));
    return d;   // {low16 = a[31:16], high16 = b[31:16]}
}
__device__ __forceinline__ uint32_t bf16x2_rn(float lo_e, float hi_e) {
    uint32_t d;   // low half = lo_e, high half = hi_e
    asm("cvt.rn.bf16x2.f32 %0, %1, %2;" : "=r"(d) : "f"(hi_e), "f"(lo_e));
    return d;
}
// split float4 (4 consecutive K elems) into 2 hi-words + 2 lo-words
__device__ __forceinline__ void split4(float4 v, uint32_t* hw, uint32_t* lw) {
    uint32_t ux = __float_as_uint(v.x), uy = __float_as_uint(v.y);
    uint32_t uz = __float_as_uint(v.z), uw = __float_as_uint(v.w);
    hw[0] = prmt_hi(ux, uy);
    hw[1] = prmt_hi(uz, uw);
    float lx = v.x - __uint_as_float(ux & 0xFFFF0000u);
    float ly = v.y - __uint_as_float(uy & 0xFFFF0000u);
    float lz = v.z - __uint_as_float(uz & 0xFFFF0000u);
    float lw_ = v.w - __uint_as_float(uw & 0xFFFF0000u);
    lw[0] = bf16x2_rn(lx, ly);
    lw[1] = bf16x2_rn(lz, lw_);
}

__device__ __forceinline__ void mma_bf16(float* d, const uint32_t* a,
                                         const uint32_t* b) {
    asm volatile(
        "mma.sync.aligned.m16n8k16.row.col.f32.bf16.bf16.f32 "
        "{%0,%1,%2,%3}, {%4,%5,%6,%7}, {%8,%9}, {%0,%1,%2,%3};"
        : "+f"(d[0]), "+f"(d[1]), "+f"(d[2]), "+f"(d[3])
        : "r"(a[0]), "r"(a[1]), "r"(a[2]), "r"(a[3]), "r"(b[0]), "r"(b[1]));
}

__global__ void __launch_bounds__(256, 2) gemm_tc(TJobs jobs, int nrows)
{
    extern __shared__ uint32_t smw[];
    uint32_t* Ah = smw;
    uint32_t* Al = smw + 128 * BA_STR;
    uint32_t* Bh = smw + 2 * 128 * BA_STR;
    uint32_t* Bl = Bh + 128 * BB_STR;

    const TJob job = jobs.j[blockIdx.y];
    const int row0 = blockIdx.x * 128;
    const int tid  = threadIdx.x;
    const int wid  = tid >> 5, lane = tid & 31;
    const int wm   = wid >> 1, wn = wid & 1;
    const int g    = lane >> 2, ti = lane & 3;

    // ---- stage + split B (128 x 128) once
#pragma unroll
    for (int i = 0; i < 16; i++) {
        int lin = tid + i * 256;
        int n   = lin >> 5;
        int kq  = (lin & 31) << 2;
        float4 v = *(const float4*)(job.B + (size_t)n * 128 + kq);
        uint32_t hw[2], lw[2];
        split4(v, hw, lw);
        int base = n * BB_STR + (kq >> 1);
        Bh[base] = hw[0]; Bh[base + 1] = hw[1];
        Bl[base] = lw[0]; Bl[base + 1] = lw[1];
    }

    float acc[2][8][4];
#pragma unroll
    for (int mt = 0; mt < 2; mt++)
#pragma unroll
        for (int nt = 0; nt < 8; nt++)
#pragma unroll
            for (int u = 0; u < 4; u++) acc[mt][nt][u] = 0.f;

    for (int c = 0; c < 2; c++) {
        // ---- stage + split A chunk (128 rows x 64 K)
#pragma unroll
        for (int i = 0; i < 8; i++) {
            int lin = tid + i * 256;
            int r   = lin >> 4;
            int kq  = (lin & 15) << 2;
            int grow = row0 + r;
            float4 v = make_float4(0.f, 0.f, 0.f, 0.f);
            if (grow < nrows)
                v = *(const float4*)(job.A + (size_t)grow * 128 + c * 64 + kq);
            uint32_t hw[2], lw[2];
            split4(v, hw, lw);
            int base = r * BA_STR + (kq >> 1);
            Ah[base] = hw[0]; Ah[base + 1] = hw[1];
            Al[base] = lw[0]; Al[base + 1] = lw[1];
        }
        __syncthreads();

#pragma unroll
        for (int s = 0; s < 4; s++) {           // k16 steps within 64-K chunk
            const int k0w = s * 8;              // word offset (2 bf16/word)
            uint32_t ah[2][4], al[2][4];
#pragma unroll
            for (int mt = 0; mt < 2; mt++) {
                int rb = wm * 32 + mt * 16;
                int i0 = (rb + g)     * BA_STR + k0w + ti;
                int i1 = (rb + g + 8) * BA_STR + k0w + ti;
                ah[mt][0] = Ah[i0];
                ah[mt][1] = Ah[i1];
                ah[mt][2] = Ah[i0 + 4];
                ah[mt][3] = Ah[i1 + 4];
                al[mt][0] = Al[i0];
                al[mt][1] = Al[i1];
                al[mt][2] = Al[i0 + 4];
                al[mt][3] = Al[i1 + 4];
            }
#pragma unroll
            for (int nt = 0; nt < 8; nt++) {
                int n = wn * 64 + nt * 8 + g;
                int b0 = n * BB_STR + c * 32 + k0w + ti;
                uint32_t bh[2], bl[2];
                bh[0] = Bh[b0]; bh[1] = Bh[b0 + 4];
                bl[0] = Bl[b0]; bl[1] = Bl[b0 + 4];
#pragma unroll
                for (int mt = 0; mt < 2; mt++) {
                    mma_bf16(acc[mt][nt], ah[mt], bh);
                    mma_bf16(acc[mt][nt], ah[mt], bl);
                    mma_bf16(acc[mt][nt], al[mt], bh);
                }
            }
        }
        __syncthreads();
    }

    // ---- epilogue
#pragma unroll
    for (int mt = 0; mt < 2; mt++) {
#pragma unroll
        for (int h = 0; h < 2; h++) {
            int grow = row0 + wm * 32 + mt * 16 + g + h * 8;
            if (grow >= nrows) continue;
            float* cp = job.C + (size_t)grow * job.ldc + job.coff + wn * 64;
#pragma unroll
            for (int nt = 0; nt < 8; nt++) {
                int col = nt * 8 + 2 * ti;
                float vx = acc[mt][nt][2 * h];
                float vy = acc[mt][nt][2 * h + 1];
                if (job.bias) {
                    vx += job.bias[wn * 64 + col];
                    vy += job.bias[wn * 64 + col + 1];
                }
                *(float2*)(cp + col) = make_float2(vx, vy);
            }
        }
    }
}

// ---------------- scalar GEMM (classifier only, ncols=40) -------------------
struct GemmJob {
    const float* A;
    const float* B;
    const float* bias;
    float*       C;
    int ldc;
    int coff;
    int ncols;
};
struct GemmJobs { GemmJob j[2]; };

__device__ __forceinline__ void fma2(unsigned long long& d,
                                     unsigned long long a, unsigned long long b) {
    asm("fma.rn.f32x2 %0, %1, %2, %0;" : "+l"(d) : "l"(a), "l"(b));
}
__device__ __forceinline__ void unpack2(unsigned long long v, float& lo, float& hi) {
    asm("mov.b64 {%0, %1}, %2;" : "=f"(lo), "=f"(hi) : "l"(v));
}

#define AS_STRIDE 260
#define BS_STRIDE 144

__global__ void __launch_bounds__(256, 2) gemm_nt(
    GemmJobs jobs, int nrows)
{
    const GemmJob job = jobs.j[blockIdx.y];
    const float* __restrict__ A    = job.A;
    const float* __restrict__ B    = job.B;
    const float* __restrict__ bias = job.bias;
    const int ncols = job.ncols;
    const int row0  = blockIdx.x * 128;

    __shared__ float As[16][AS_STRIDE];
    __shared__ float Bs[16][BS_STRIDE];

    const int t  = threadIdx.x;
    const int tx = t & 15;
    const int ty = t >> 4;

    unsigned long long acc[8][4];
#pragma unroll
    for (int y = 0; y < 8; y++)
#pragma unroll
        for (int xp = 0; xp < 4; xp++) acc[y][xp] = 0ULL;

    const int b_base = tx * 8 + ((tx >> 2) << 2);

    for (int k0 = 0; k0 < 128; k0 += 16) {
#pragma unroll
        for (int i = 0; i < 2; i++) {
            int lin = t + i * 256;
            int r   = lin >> 2;
            int kq  = lin & 3;
            float4 v = make_float4(0.f, 0.f, 0.f, 0.f);
            int grow = row0 + r;
            if (grow < nrows)
                v = *(const float4*)(A + (size_t)grow * 128 + k0 + kq * 4);
            *(float2*)&As[kq * 4 + 0][2 * r] = make_float2(v.x, v.x);
            *(float2*)&As[kq * 4 + 1][2 * r] = make_float2(v.y, v.y);
            *(float2*)&As[kq * 4 + 2][2 * r] = make_float2(v.z, v.z);
            *(float2*)&As[kq * 4 + 3][2 * r] = make_float2(v.w, v.w);
        }
#pragma unroll
        for (int i = 0; i < 2; i++) {
            int lin = t + i * 256;
            int j   = lin >> 2;
            int kq  = lin & 3;
            float4 v = make_float4(0.f, 0.f, 0.f, 0.f);
            if (j < ncols)
                v = *(const float4*)(B + (size_t)j * 128 + k0 + kq * 4);
            int pj = j + ((j >> 5) << 2);
            Bs[kq * 4 + 0][pj] = v.x;
            Bs[kq * 4 + 1][pj] = v.y;
            Bs[kq * 4 + 2][pj] = v.z;
            Bs[kq * 4 + 3][pj] = v.w;
        }
        __syncthreads();
#pragma unroll
        for (int kk = 0; kk < 16; kk++) {
            unsigned long long ad[8], bp[4];
            const ulonglong2* ap = (const ulonglong2*)&As[kk][ty * 16];
            const ulonglong2* bq = (const ulonglong2*)&Bs[kk][b_base];
#pragma unroll
            for (int i = 0; i < 4; i++) {
                ulonglong2 u = ap[i];
                ad[2 * i]     = u.x;
                ad[2 * i + 1] = u.y;
            }
#pragma unroll
            for (int i = 0; i < 2; i++) {
                ulonglong2 u = bq[i];
                bp[2 * i]     = u.x;
                bp[2 * i + 1] = u.y;
            }
#pragma unroll
            for (int y = 0; y < 8; y++)
#pragma unroll
                for (int xp = 0; xp < 4; xp++)
                    fma2(acc[y][xp], ad[y], bp[xp]);
        }
        __syncthreads();
    }

#pragma unroll
    for (int y = 0; y < 8; y++) {
        int grow = row0 + ty * 8 + y;
        if (grow >= nrows) continue;
        float* cp = job.C + (size_t)grow * job.ldc + job.coff;
        float c[8];
#pragma unroll
        for (int xp = 0; xp < 4; xp++)
            unpack2(acc[y][xp], c[2 * xp], c[2 * xp + 1]);
#pragma unroll
        for (int xq = 0; xq < 2; xq++) {
            int col = tx * 8 + xq * 4;
            if (col >= ncols) continue;
            float4 v = make_float4(c[xq * 4 + 0], c[xq * 4 + 1],
                                   c[xq * 4 + 2], c[xq * 4 + 3]);
            if (bias) {
                v.x += bias[col + 0];
                v.y += bias[col + 1];
                v.z += bias[col + 2];
                v.w += bias[col + 3];
            }
            *(float4*)(cp + col) = v;
        }
    }
}

// ---------------- BatchNorm --------------------------------------------------
__global__ void bn_stats(const float* __restrict__ X, float* __restrict__ stats)
{
    int c  = threadIdx.x;
    int r0 = blockIdx.x * 64;
    int r1 = min(r0 + 64, N_NODES);
    float s = 0.f, q = 0.f;
    for (int r = r0; r < r1; r++) {
        float v = X[(size_t)r * 128 + c];
        s += v;
        q = fmaf(v, v, q);
    }
    atomicAdd(&stats[c], s);
    atomicAdd(&stats[128 + c], q);
}

__global__ void bn_apply(const float4* __restrict__ X, const float* __restrict__ stats,
                         const float* __restrict__ gamma, const float* __restrict__ beta,
                         const float4* __restrict__ residual, float4* __restrict__ out)
{
    int i = blockIdx.x * blockDim.x + threadIdx.x;
    if (i >= N_NODES * 32) return;
    int c0 = (i & 31) * 4;
    const float invN = 1.f / (float)N_NODES;
    float4 v = X[i];
    float r[4] = {v.x, v.y, v.z, v.w};
#pragma unroll
    for (int k = 0; k < 4; k++) {
        int c = c0 + k;
        float m   = stats[c] * invN;
        float var = stats[128 + c] * invN - m * m;
        float u = gamma[c] * (r[k] - m) * rsqrtf(var + 1e-5f) + beta[c];
        r[k] = fmaxf(u, 0.f);
    }
    float4 o = make_float4(r[0], r[1], r[2], r[3]);
    if (residual) {
        float4 rv = residual[i];
        o.x += rv.x; o.y += rv.y; o.z += rv.z; o.w += rv.w;
    }
    out[i] = o;
}

// ---------------- small utility kernels -------------------------------------
__global__ void zero_f(float* __restrict__ p, int n)
{
    int i = blockIdx.x * blockDim.x + threadIdx.x;
    if (i < n) p[i] = 0.f;
}

__global__ void recip_f(float* __restrict__ p, int n)
{
    int i = blockIdx.x * blockDim.x + threadIdx.x;
    if (i < n) p[i] = 1.f / p[i];
}

__global__ void init_counts_k(int* __restrict__ cnt)
{
    int i = blockIdx.x * blockDim.x + threadIdx.x;
    if (i < N_NODES) cnt[i] = 1;   // self loop
}

__global__ void hist_k(const int* __restrict__ ei1, int* __restrict__ cnt)
{
    int e = blockIdx.x * blockDim.x + threadIdx.x;
    if (e < N_EDGES) atomicAdd(&cnt[ei1[e]], 1);
}

__global__ void scan_k(const int* __restrict__ cnt, int* __restrict__ off,
                       int* __restrict__ cur)
{
    __shared__ int sh[1024];
    const int CH = (N_NODES + 1023) / 1024;
    int t = threadIdx.x;
    int base = t * CH;
    int local = 0;
    for (int i = 0; i < CH; i++) {
        int idx = base + i;
        if (idx < N_NODES) local += cnt[idx];
    }
    sh[t] = local;
    __syncthreads();
    for (int o = 1; o < 1024; o <<= 1) {
        int v = 0;
        if (t >= o) v = sh[t - o];
        __syncthreads();
        if (t >= o) sh[t] += v;
        __syncthreads();
    }
    int run = (t == 0) ? 0 : sh[t - 1];
    for (int i = 0; i < CH; i++) {
        int idx = base + i;
        if (idx < N_NODES) {
            off[idx] = run;
            cur[idx] = run;
            run += cnt[idx];
        }
    }
    if (t == 0) off[N_NODES] = EAUG;
}

__global__ void csr_fill_k(const int* __restrict__ ei1, int* __restrict__ cur,
                           int* __restrict__ eid)
{
    int e = blockIdx.x * blockDim.x + threadIdx.x;
    if (e >= EAUG) return;
    int c = (e < N_EDGES) ? ei1[e] : (e - N_EDGES);
    int pos = atomicAdd(&cur[c], 1);
    eid[pos] = e;
}

// ---------------- per-node Wh dots -------------------------------------------
__global__ void pq_kernel(const float* __restrict__ G, const float* __restrict__ Wh,
                          float2* __restrict__ PQ)
{
    int node = (blockIdx.x * blockDim.x + threadIdx.x) >> 5;
    int lane = threadIdx.x & 31;
    if (node >= N_NODES) return;
    float4 xg = ((const float4*)(G + (size_t)node * 256))[lane];
    float4 a  = ((const float4*)Wh)[lane];
    float4 b  = ((const float4*)Wh)[lane + 32];
    float p = xg.x * a.x + xg.y * a.y + xg.z * a.z + xg.w * a.w;
    float q = xg.x * b.x + xg.y * b.y + xg.z * b.z + xg.w * b.w;
#pragma unroll
    for (int o = 16; o > 0; o >>= 1) {
        p += __shfl_xor_sync(0xffffffffu, p, o);
        q += __shfl_xor_sync(0xffffffffu, q, o);
    }
    if (lane == 0) PQ[node] = make_float2(p, q);
}

// ---------------- edge pass 1 -------------------------------------------------
__global__ void edge_pass1(const float* __restrict__ G,
                           const int* __restrict__ ei0, const int* __restrict__ ei1,
                           const float2* __restrict__ PQ, const float* __restrict__ bh,
                           float2* __restrict__ s_buf, float* __restrict__ Z)
{
    int gw   = (blockIdx.x * blockDim.x + threadIdx.x) >> 5;
    int lane = threadIdx.x & 31;
    if (gw >= EAUG) return;
    int r, c;
    if (gw < N_EDGES) { r = ei0[gw]; c = ei1[gw]; }
    else              { r = gw - N_EDGES; c = r; }

    float4 xr = ((const float4*)(G + (size_t)r * 256))[lane];
    float4 xc = ((const float4*)(G + (size_t)c * 256))[lane];

    float dx = xr.x - xc.x, dy = xr.y - xc.y, dz = xr.z - xc.z, dw = xr.w - xc.w;
    float ss = dx * dx + dy * dy + dz * dz + dw * dw;
#pragma unroll
    for (int o = 16; o > 0; o >>= 1)
        ss += __shfl_xor_sync(0xffffffffu, ss, o);
    if (lane == 0) {
        float g = sqrtf(ss + 1e-12f);
        float t = PQ[r].x + PQ[c].y + bh[0];
        float h = fmaxf(t, 0.f) + log1pf(__expf(-fabsf(t)));   // softplus
        float s = 1.f / (1.f + __expf(g + h));                 // sigmoid(-(g+h))
        float es = __expf(s);
        float ed = __expf(1.f - s);
        s_buf[gw] = make_float2(es, ed);
        atomicAdd(&Z[r],           es);
        atomicAdd(&Z[N_NODES + r], ed);
    }
}

// ---------------- aggregation of RAW input features -------------------------
__global__ void agg_k(const float* __restrict__ X,
                      const int* __restrict__ off, const int* __restrict__ eid,
                      const int* __restrict__ ei0,
                      const float2* __restrict__ s_buf, const float* __restrict__ invZ,
                      float* __restrict__ SC, float* __restrict__ SD)
{
    int node = (blockIdx.x * blockDim.x + threadIdx.x) >> 5;
    int lane = threadIdx.x & 31;
    if (node >= N_NODES) return;

    int p0 = off[node], p1 = off[node + 1];
    float4 ac = make_float4(0.f, 0.f, 0.f, 0.f);
    float4 ad = make_float4(0.f, 0.f, 0.f, 0.f);
    for (int p = p0; p < p1; p++) {
        int e = eid[p];
        int r = (e < N_EDGES) ? ei0[e] : (e - N_EDGES);
        float2 es = s_buf[e];
        float wc = es.x * invZ[r];
        float wd = es.y * invZ[N_NODES + r];
        float4 v = ((const float4*)(X + (size_t)r * 128))[lane];
        ac.x = fmaf(wc, v.x, ac.x); ac.y = fmaf(wc, v.y, ac.y);
        ac.z = fmaf(wc, v.z, ac.z); ac.w = fmaf(wc, v.w, ac.w);
        ad.x = fmaf(wd, v.x, ad.x); ad.y = fmaf(wd, v.y, ad.y);
        ad.z = fmaf(wd, v.z, ad.z); ad.w = fmaf(wd, v.w, ad.w);
    }
    ((float4*)(SC + (size_t)node * 128))[lane] = ac;
    ((float4*)(SD + (size_t)node * 128))[lane] = ad;
}

// ---------------- gate + combine + residual ----------------------------------
__global__ void gate_k(const float* __restrict__ OC, const float* __restrict__ OD,
                       const float* __restrict__ G,
                       const float* __restrict__ Wgate, const float* __restrict__ bgate,
                       const float* __restrict__ residual, float* __restrict__ out)
{
    int node = (blockIdx.x * blockDim.x + threadIdx.x) >> 5;
    int lane = threadIdx.x & 31;
    if (node >= N_NODES) return;

    float4 ac = ((const float4*)(OC + (size_t)node * 128))[lane];
    float4 ad = ((const float4*)(OD + (size_t)node * 128))[lane];
    float4 sf = ((const float4*)(G + (size_t)node * 256 + 128))[lane];

    float l[3];
#pragma unroll
    for (int k = 0; k < 3; k++) {
        float4 w0 = ((const float4*)(Wgate + k * 384))[lane];
        float4 w1 = ((const float4*)(Wgate + k * 384 + 128))[lane];
        float4 w2 = ((const float4*)(Wgate + k * 384 + 256))[lane];
        l[k] = w0.x * ac.x + w0.y * ac.y + w0.z * ac.z + w0.w * ac.w
             + w1.x * ad.x + w1.y * ad.y + w1.z * ad.z + w1.w * ad.w
             + w2.x * sf.x + w2.y * sf.y + w2.z * sf.z + w2.w * sf.w;
    }
#pragma unroll
    for (int o = 16; o > 0; o >>= 1) {
        l[0] += __shfl_xor_sync(0xffffffffu, l[0], o);
        l[1] += __shfl_xor_sync(0xffffffffu, l[1], o);
        l[2] += __shfl_xor_sync(0xffffffffu, l[2], o);
    }
    l[0] += bgate[0]; l[1] += bgate[1]; l[2] += bgate[2];
    float m  = fmaxf(l[0], fmaxf(l[1], l[2]));
    float e0 = __expf(l[0] - m), e1 = __expf(l[1] - m), e2 = __expf(l[2] - m);
    float inv = 1.f / (e0 + e1 + e2);
    float g0 = e0 * inv, g1 = e1 * inv, g2 = e2 * inv;

    float4 o4;
    o4.x = g0 * ac.x + g1 * ad.x + g2 * sf.x;
    o4.y = g0 * ac.y + g1 * ad.y + g2 * sf.y;
    o4.z = g0 * ac.z + g1 * ad.z + g2 * sf.z;
    o4.w = g0 * ac.w + g1 * ad.w + g2 * sf.w;
    if (residual) {
        float4 rv = ((const float4*)(residual + (size_t)node * 128))[lane];
        o4.x += rv.x; o4.y += rv.y; o4.z += rv.z; o4.w += rv.w;
    }
    ((float4*)(out + (size_t)node * 128))[lane] = o4;
}

// ---------------- launch ------------------------------------------------------
extern "C" void kernel_launch(void* const* d_in, const int* in_sizes, int n_in,
                              void* d_out, int out_size)
{
    (void)in_sizes; (void)n_in; (void)out_size;
    const float* x       = (const float*)d_in[0];
    const int*   ei      = (const int*)d_in[1];
    const float* mlp_W   = (const float*)d_in[2];
    const float* mlp_b   = (const float*)d_in[3];
    const float* mlp_g   = (const float*)d_in[4];
    const float* mlp_be  = (const float*)d_in[5];
    const float* bn0_g   = (const float*)d_in[6];
    const float* bn0_be  = (const float*)d_in[7];
    const float* cls_W   = (const float*)d_in[8];
    const float* cls_b   = (const float*)d_in[9];
    const float* Wg[2]    = {(const float*)d_in[10], (const float*)d_in[19]};
    const float* Wh[2]    = {(const float*)d_in[11], (const float*)d_in[20]};
    const float* bh[2]    = {(const float*)d_in[12], (const float*)d_in[21]};
    const float* Wcon[2]  = {(const float*)d_in[13], (const float*)d_in[22]};
    const float* Wdis[2]  = {(const float*)d_in[14], (const float*)d_in[23]};
    const float* Wself[2] = {(const float*)d_in[15], (const float*)d_in[24]};
    const float* bself[2] = {(const float*)d_in[16], (const float*)d_in[25]};
    const float* Wgate[2] = {(const float*)d_in[17], (const float*)d_in[26]};
    const float* bgate[2] = {(const float*)d_in[18], (const float*)d_in[27]};
    const int* ei0 = ei;
    const int* ei1 = ei + N_EDGES;
    float* out = (float*)d_out;

    float *pH0, *pX1, *pTmp, *pG, *pSC, *pSD, *pZ, *pStats;
    float2 *pS, *pPQ;
    int *pOff, *pCur, *pCnt, *pEid;
    cudaGetSymbolAddress((void**)&pH0,   d_h0);
    cudaGetSymbolAddress((void**)&pX1,   d_x1);
    cudaGetSymbolAddress((void**)&pTmp,  d_tmp);
    cudaGetSymbolAddress((void**)&pG,    d_G);
    cudaGetSymbolAddress((void**)&pSC,   d_SC);
    cudaGetSymbolAddress((void**)&pSD,   d_SD);
    cudaGetSymbolAddress((void**)&pPQ,   d_PQ);
    cudaGetSymbolAddress((void**)&pS,    d_s);
    cudaGetSymbolAddress((void**)&pZ,    d_Z);
    cudaGetSymbolAddress((void**)&pStats,d_stats);
    cudaGetSymbolAddress((void**)&pOff,  d_off);
    cudaGetSymbolAddress((void**)&pCur,  d_cur);
    cudaGetSymbolAddress((void**)&pCnt,  d_cnt);
    cudaGetSymbolAddress((void**)&pEid,  d_eid);

    cudaFuncSetAttribute(gemm_tc, cudaFuncAttributeMaxDynamicSharedMemorySize,
                         BSM_TOTAL);

    const int GR = (N_NODES + 127) / 128;          // 391 row blocks
    const int NODE_WARPS = (N_NODES * 32 + 255) / 256;

    // ---- MLP + BN + relu -> h0
    {
        TJobs tj = {};
        tj.j[0] = {x, mlp_W, mlp_b, pTmp, 128, 0};
        tj.j[1] = tj.j[0];
        gemm_tc<<<dim3(GR, 1), 256, BSM_TOTAL>>>(tj, N_NODES);
    }
    zero_f<<<1, 256>>>(pStats, 256);
    bn_stats<<<(N_NODES + 63) / 64, 128>>>(pTmp, pStats);
    bn_apply<<<NODE_WARPS, 256>>>((const float4*)pTmp, pStats,
                                  mlp_g, mlp_be, nullptr, (float4*)pH0);

    // ---- CSR by col (shared by both layers)
    init_counts_k<<<(N_NODES + 255) / 256, 256>>>(pCnt);
    hist_k<<<(N_EDGES + 255) / 256, 256>>>(ei1, pCnt);
    scan_k<<<1, 1024>>>(pCnt, pOff, pCur);
    csr_fill_k<<<(EAUG + 255) / 256, 256>>>(ei1, pCur, pEid);

    // ---- conv layers
    const float* lin[2] = {pH0, pX1};
    for (int l = 0; l < 2; l++) {
        const float* X = lin[l];
        {   // G = [X@Wg.T | X@Wself.T + bself]
            TJobs tj = {};
            tj.j[0] = {X, Wg[l],    nullptr,  pG, 256, 0};
            tj.j[1] = {X, Wself[l], bself[l], pG, 256, 128};
            gemm_tc<<<dim3(GR, 2), 256, BSM_TOTAL>>>(tj, N_NODES);
        }
        pq_kernel<<<NODE_WARPS, 256>>>(pG, Wh[l], pPQ);
        zero_f<<<(2 * N_NODES + 255) / 256, 256>>>(pZ, 2 * N_NODES);
        edge_pass1<<<(EAUG * 32 + 255) / 256, 256>>>(pG, ei0, ei1, pPQ, bh[l],
                                                     pS, pZ);
        recip_f<<<(2 * N_NODES + 255) / 256, 256>>>(pZ, 2 * N_NODES);
        agg_k<<<NODE_WARPS, 256>>>(X, pOff, pEid, ei0, pS, pZ, pSC, pSD);
        {   // SC = SC@Wcon.T, SD = SD@Wdis.T (in place; rows disjoint per CTA)
            TJobs tj = {};
            tj.j[0] = {pSC, Wcon[l], nullptr, pSC, 128, 0};
            tj.j[1] = {pSD, Wdis[l], nullptr, pSD, 128, 0};
            gemm_tc<<<dim3(GR, 2), 256, BSM_TOTAL>>>(tj, N_NODES);
        }
        gate_k<<<NODE_WARPS, 256>>>(pSC, pSD, pG, Wgate[l], bgate[l],
                                    (l == 0) ? nullptr : pX1, pTmp);
        if (l == 0) {
            zero_f<<<1, 256>>>(pStats, 256);
            bn_stats<<<(N_NODES + 63) / 64, 128>>>(pTmp, pStats);
            bn_apply<<<NODE_WARPS, 256>>>((const float4*)pTmp, pStats,
                                          bn0_g, bn0_be,
                                          (const float4*)pH0, (float4*)pX1);
        }
    }

    // ---- classifier: out = x2 @ cls_W.T + cls_b   (x2 lives in d_tmp)
    {
        GemmJobs gj = {};
        gj.j[0] = {pTmp, cls_W, cls_b, out, 40, 0, 40};
        gj.j[1] = gj.j[0];
        gemm_nt<<<dim3(GR, 1), 256>>>(gj, N_NODES);
    }
}

// round 15
// speedup vs baseline: 1.0860x; 1.0200x over previous
#include <cuda_runtime.h>
#include <cstdint>

#define N_NODES 50000
#define N_EDGES 800000
#define EAUG    (N_EDGES + N_NODES)
#define HID     128
#define NCLS    40

// ---------------- scratch (static device globals; no runtime alloc) --------
__device__ float  d_h0 [N_NODES * HID];
__device__ float  d_x1 [N_NODES * HID];
__device__ float  d_tmp[N_NODES * HID];
__device__ float  d_G  [(size_t)N_NODES * 256];   // [xg | xself]
__device__ float  d_SC [N_NODES * HID];
__device__ float  d_SD [N_NODES * HID];
__device__ float2 d_PQ [N_NODES];
__device__ float2 d_s  [EAUG];                    // {exp(s), exp(1-s)}
__device__ float  d_Z  [2 * N_NODES];
__device__ float  d_stats[2 * HID];
__device__ int    d_off [N_NODES + 1];
__device__ int    d_cur [N_NODES];
__device__ int    d_cnt [N_NODES];
__device__ int    d_eid [EAUG];

// ---------------- side stream + events (created once; no device memory) ----
static cudaStream_t g_s1;
static cudaEvent_t  g_ev[6];
struct SideStreamInit {
    SideStreamInit() {
        cudaStreamCreateWithFlags(&g_s1, cudaStreamNonBlocking);
        for (int i = 0; i < 6; i++)
            cudaEventCreateWithFlags(&g_ev[i], cudaEventDisableTiming);
    }
};
static SideStreamInit g_side_init;

// ============================================================================
// Tensor-core GEMM via mma.sync m16n8k16 bf16, 3-term split done at staging:
//   x = hi + lo;  hi = trunc-bf16(x) (top 16 bits, PRMT-packed);
//   lo = rn-bf16(x - hi).  D = Ah*Bh + Ah*Bl + Al*Bh  (lo*lo dropped ~2^-18).
// 128x128 tile, K=128 (A staged per 64-K chunk, B staged once), 8 warps 4x2.
// Smem word-strides % 32 == 4 -> conflict-free 32-bit fragment loads.
// ============================================================================
struct TJob {
    const float* A;
    const float* B;
    const float* bias;
    float*       C;
    int ldc;
    int coff;
};
struct TJobs { TJob j[2]; };

#define BA_STR 36   // uint32 words per A smem row (32 data + 4 pad)
#define BB_STR 68   // uint32 words per B smem row (64 data + 4 pad)
#define BSM_TOTAL ((2*128*BA_STR + 2*128*BB_STR) * 4)   // 106496 bytes

__device__ __forceinline__ uint32_t prmt_hi(uint32_t a, uint32_t b) {
    uint32_t d;
    asm("prmt.b32 %0, %1, %2, 0x7632;" : "=r"(d) : "r"(a), "r"(b));
    return d;   // {low16 = a[31:16], high16 = b[31:16]}
}
__device__ __forceinline__ uint32_t bf16x2_rn(float lo_e, float hi_e) {
    uint32_t d;   // low half = lo_e, high half = hi_e
    asm("cvt.rn.bf16x2.f32 %0, %1, %2;" : "=r"(d) : "f"(hi_e), "f"(lo_e));
    return d;
}
// split float4 (4 consecutive K elems) into 2 hi-words + 2 lo-words
__device__ __forceinline__ void split4(float4 v, uint32_t* hw, uint32_t* lw) {
    uint32_t ux = __float_as_uint(v.x), uy = __float_as_uint(v.y);
    uint32_t uz = __float_as_uint(v.z), uw = __float_as_uint(v.w);
    hw[0] = prmt_hi(ux, uy);
    hw[1] = prmt_hi(uz, uw);
    float lx = v.x - __uint_as_float(ux & 0xFFFF0000u);
    float ly = v.y - __uint_as_float(uy & 0xFFFF0000u);
    float lz = v.z - __uint_as_float(uz & 0xFFFF0000u);
    float lw_ = v.w - __uint_as_float(uw & 0xFFFF0000u);
    lw[0] = bf16x2_rn(lx, ly);
    lw[1] = bf16x2_rn(lz, lw_);
}

__device__ __forceinline__ void mma_bf16(float* d, const uint32_t* a,
                                         const uint32_t* b) {
    asm volatile(
        "mma.sync.aligned.m16n8k16.row.col.f32.bf16.bf16.f32 "
        "{%0,%1,%2,%3}, {%4,%5,%6,%7}, {%8,%9}, {%0,%1,%2,%3};"
        : "+f"(d[0]), "+f"(d[1]), "+f"(d[2]), "+f"(d[3])
        : "r"(a[0]), "r"(a[1]), "r"(a[2]), "r"(a[3]), "r"(b[0]), "r"(b[1]));
}

__global__ void __launch_bounds__(256, 2) gemm_tc(TJobs jobs, int nrows)
{
    extern __shared__ uint32_t smw[];
    uint32_t* Ah = smw;
    uint32_t* Al = smw + 128 * BA_STR;
    uint32_t* Bh = smw + 2 * 128 * BA_STR;
    uint32_t* Bl = Bh + 128 * BB_STR;

    const TJob job = jobs.j[blockIdx.y];
    const int row0 = blockIdx.x * 128;
    const int tid  = threadIdx.x;
    const int wid  = tid >> 5, lane = tid & 31;
    const int wm   = wid >> 1, wn = wid & 1;
    const int g    = lane >> 2, ti = lane & 3;

    // ---- stage + split B (128 x 128) once
#pragma unroll
    for (int i = 0; i < 16; i++) {
        int lin = tid + i * 256;
        int n   = lin >> 5;
        int kq  = (lin & 31) << 2;
        float4 v = *(const float4*)(job.B + (size_t)n * 128 + kq);
        uint32_t hw[2], lw[2];
        split4(v, hw, lw);
        int base = n * BB_STR + (kq >> 1);
        Bh[base] = hw[0]; Bh[base + 1] = hw[1];
        Bl[base] = lw[0]; Bl[base + 1] = lw[1];
    }

    float acc[2][8][4];
#pragma unroll
    for (int mt = 0; mt < 2; mt++)
#pragma unroll
        for (int nt = 0; nt < 8; nt++)
#pragma unroll
            for (int u = 0; u < 4; u++) acc[mt][nt][u] = 0.f;

    for (int c = 0; c < 2; c++) {
        // ---- stage + split A chunk (128 rows x 64 K)
#pragma unroll
        for (int i = 0; i < 8; i++) {
            int lin = tid + i * 256;
            int r   = lin >> 4;
            int kq  = (lin & 15) << 2;
            int grow = row0 + r;
            float4 v = make_float4(0.f, 0.f, 0.f, 0.f);
            if (grow < nrows)
                v = *(const float4*)(job.A + (size_t)grow * 128 + c * 64 + kq);
            uint32_t hw[2], lw[2];
            split4(v, hw, lw);
            int base = r * BA_STR + (kq >> 1);
            Ah[base] = hw[0]; Ah[base + 1] = hw[1];
            Al[base] = lw[0]; Al[base + 1] = lw[1];
        }
        __syncthreads();

#pragma unroll
        for (int s = 0; s < 4; s++) {           // k16 steps within 64-K chunk
            const int k0w = s * 8;              // word offset (2 bf16/word)
            uint32_t ah[2][4], al[2][4];
#pragma unroll
            for (int mt = 0; mt < 2; mt++) {
                int rb = wm * 32 + mt * 16;
                int i0 = (rb + g)     * BA_STR + k0w + ti;
                int i1 = (rb + g + 8) * BA_STR + k0w + ti;
                ah[mt][0] = Ah[i0];
                ah[mt][1] = Ah[i1];
                ah[mt][2] = Ah[i0 + 4];
                ah[mt][3] = Ah[i1 + 4];
                al[mt][0] = Al[i0];
                al[mt][1] = Al[i1];
                al[mt][2] = Al[i0 + 4];
                al[mt][3] = Al[i1 + 4];
            }
#pragma unroll
            for (int nt = 0; nt < 8; nt++) {
                int n = wn * 64 + nt * 8 + g;
                int b0 = n * BB_STR + c * 32 + k0w + ti;
                uint32_t bh[2], bl[2];
                bh[0] = Bh[b0]; bh[1] = Bh[b0 + 4];
                bl[0] = Bl[b0]; bl[1] = Bl[b0 + 4];
#pragma unroll
                for (int mt = 0; mt < 2; mt++) {
                    mma_bf16(acc[mt][nt], ah[mt], bh);
                    mma_bf16(acc[mt][nt], ah[mt], bl);
                    mma_bf16(acc[mt][nt], al[mt], bh);
                }
            }
        }
        __syncthreads();
    }

    // ---- epilogue
#pragma unroll
    for (int mt = 0; mt < 2; mt++) {
#pragma unroll
        for (int h = 0; h < 2; h++) {
            int grow = row0 + wm * 32 + mt * 16 + g + h * 8;
            if (grow >= nrows) continue;
            float* cp = job.C + (size_t)grow * job.ldc + job.coff + wn * 64;
#pragma unroll
            for (int nt = 0; nt < 8; nt++) {
                int col = nt * 8 + 2 * ti;
                float vx = acc[mt][nt][2 * h];
                float vy = acc[mt][nt][2 * h + 1];
                if (job.bias) {
                    vx += job.bias[wn * 64 + col];
                    vy += job.bias[wn * 64 + col + 1];
                }
                *(float2*)(cp + col) = make_float2(vx, vy);
            }
        }
    }
}

// ---------------- scalar GEMM (classifier only, ncols=40) -------------------
struct GemmJob {
    const float* A;
    const float* B;
    const float* bias;
    float*       C;
    int ldc;
    int coff;
    int ncols;
};
struct GemmJobs { GemmJob j[2]; };

__device__ __forceinline__ void fma2(unsigned long long& d,
                                     unsigned long long a, unsigned long long b) {
    asm("fma.rn.f32x2 %0, %1, %2, %0;" : "+l"(d) : "l"(a), "l"(b));
}
__device__ __forceinline__ void unpack2(unsigned long long v, float& lo, float& hi) {
    asm("mov.b64 {%0, %1}, %2;" : "=f"(lo), "=f"(hi) : "l"(v));
}

#define AS_STRIDE 260
#define BS_STRIDE 144

__global__ void __launch_bounds__(256, 2) gemm_nt(
    GemmJobs jobs, int nrows)
{
    const GemmJob job = jobs.j[blockIdx.y];
    const float* __restrict__ A    = job.A;
    const float* __restrict__ B    = job.B;
    const float* __restrict__ bias = job.bias;
    const int ncols = job.ncols;
    const int row0  = blockIdx.x * 128;

    __shared__ float As[16][AS_STRIDE];
    __shared__ float Bs[16][BS_STRIDE];

    const int t  = threadIdx.x;
    const int tx = t & 15;
    const int ty = t >> 4;

    unsigned long long acc[8][4];
#pragma unroll
    for (int y = 0; y < 8; y++)
#pragma unroll
        for (int xp = 0; xp < 4; xp++) acc[y][xp] = 0ULL;

    const int b_base = tx * 8 + ((tx >> 2) << 2);

    for (int k0 = 0; k0 < 128; k0 += 16) {
#pragma unroll
        for (int i = 0; i < 2; i++) {
            int lin = t + i * 256;
            int r   = lin >> 2;
            int kq  = lin & 3;
            float4 v = make_float4(0.f, 0.f, 0.f, 0.f);
            int grow = row0 + r;
            if (grow < nrows)
                v = *(const float4*)(A + (size_t)grow * 128 + k0 + kq * 4);
            *(float2*)&As[kq * 4 + 0][2 * r] = make_float2(v.x, v.x);
            *(float2*)&As[kq * 4 + 1][2 * r] = make_float2(v.y, v.y);
            *(float2*)&As[kq * 4 + 2][2 * r] = make_float2(v.z, v.z);
            *(float2*)&As[kq * 4 + 3][2 * r] = make_float2(v.w, v.w);
        }
#pragma unroll
        for (int i = 0; i < 2; i++) {
            int lin = t + i * 256;
            int j   = lin >> 2;
            int kq  = lin & 3;
            float4 v = make_float4(0.f, 0.f, 0.f, 0.f);
            if (j < ncols)
                v = *(const float4*)(B + (size_t)j * 128 + k0 + kq * 4);
            int pj = j + ((j >> 5) << 2);
            Bs[kq * 4 + 0][pj] = v.x;
            Bs[kq * 4 + 1][pj] = v.y;
            Bs[kq * 4 + 2][pj] = v.z;
            Bs[kq * 4 + 3][pj] = v.w;
        }
        __syncthreads();
#pragma unroll
        for (int kk = 0; kk < 16; kk++) {
            unsigned long long ad[8], bp[4];
            const ulonglong2* ap = (const ulonglong2*)&As[kk][ty * 16];
            const ulonglong2* bq = (const ulonglong2*)&Bs[kk][b_base];
#pragma unroll
            for (int i = 0; i < 4; i++) {
                ulonglong2 u = ap[i];
                ad[2 * i]     = u.x;
                ad[2 * i + 1] = u.y;
            }
#pragma unroll
            for (int i = 0; i < 2; i++) {
                ulonglong2 u = bq[i];
                bp[2 * i]     = u.x;
                bp[2 * i + 1] = u.y;
            }
#pragma unroll
            for (int y = 0; y < 8; y++)
#pragma unroll
                for (int xp = 0; xp < 4; xp++)
                    fma2(acc[y][xp], ad[y], bp[xp]);
        }
        __syncthreads();
    }

#pragma unroll
    for (int y = 0; y < 8; y++) {
        int grow = row0 + ty * 8 + y;
        if (grow >= nrows) continue;
        float* cp = job.C + (size_t)grow * job.ldc + job.coff;
        float c[8];
#pragma unroll
        for (int xp = 0; xp < 4; xp++)
            unpack2(acc[y][xp], c[2 * xp], c[2 * xp + 1]);
#pragma unroll
        for (int xq = 0; xq < 2; xq++) {
            int col = tx * 8 + xq * 4;
            if (col >= ncols) continue;
            float4 v = make_float4(c[xq * 4 + 0], c[xq * 4 + 1],
                                   c[xq * 4 + 2], c[xq * 4 + 3]);
            if (bias) {
                v.x += bias[col + 0];
                v.y += bias[col + 1];
                v.z += bias[col + 2];
                v.w += bias[col + 3];
            }
            *(float4*)(cp + col) = v;
        }
    }
}

// ---------------- BatchNorm --------------------------------------------------
__global__ void bn_stats(const float* __restrict__ X, float* __restrict__ stats)
{
    int c  = threadIdx.x;
    int r0 = blockIdx.x * 64;
    int r1 = min(r0 + 64, N_NODES);
    float s = 0.f, q = 0.f;
    for (int r = r0; r < r1; r++) {
        float v = X[(size_t)r * 128 + c];
        s += v;
        q = fmaf(v, v, q);
    }
    atomicAdd(&stats[c], s);
    atomicAdd(&stats[128 + c], q);
}

__global__ void bn_apply(const float4* __restrict__ X, const float* __restrict__ stats,
                         const float* __restrict__ gamma, const float* __restrict__ beta,
                         const float4* __restrict__ residual, float4* __restrict__ out)
{
    int i = blockIdx.x * blockDim.x + threadIdx.x;
    if (i >= N_NODES * 32) return;
    int c0 = (i & 31) * 4;
    const float invN = 1.f / (float)N_NODES;
    float4 v = X[i];
    float r[4] = {v.x, v.y, v.z, v.w};
#pragma unroll
    for (int k = 0; k < 4; k++) {
        int c = c0 + k;
        float m   = stats[c] * invN;
        float var = stats[128 + c] * invN - m * m;
        float u = gamma[c] * (r[k] - m) * rsqrtf(var + 1e-5f) + beta[c];
        r[k] = fmaxf(u, 0.f);
    }
    float4 o = make_float4(r[0], r[1], r[2], r[3]);
    if (residual) {
        float4 rv = residual[i];
        o.x += rv.x; o.y += rv.y; o.z += rv.z; o.w += rv.w;
    }
    out[i] = o;
}

// ---------------- small utility kernels -------------------------------------
__global__ void zero_f(float* __restrict__ p, int n)
{
    int i = blockIdx.x * blockDim.x + threadIdx.x;
    if (i < n) p[i] = 0.f;
}

__global__ void recip_f(float* __restrict__ p, int n)
{
    int i = blockIdx.x * blockDim.x + threadIdx.x;
    if (i < n) p[i] = 1.f / p[i];
}

__global__ void init_counts_k(int* __restrict__ cnt)
{
    int i = blockIdx.x * blockDim.x + threadIdx.x;
    if (i < N_NODES) cnt[i] = 1;   // self loop
}

__global__ void hist_k(const int* __restrict__ ei1, int* __restrict__ cnt)
{
    int e = blockIdx.x * blockDim.x + threadIdx.x;
    if (e < N_EDGES) atomicAdd(&cnt[ei1[e]], 1);
}

__global__ void scan_k(const int* __restrict__ cnt, int* __restrict__ off,
                       int* __restrict__ cur)
{
    __shared__ int sh[1024];
    const int CH = (N_NODES + 1023) / 1024;
    int t = threadIdx.x;
    int base = t * CH;
    int local = 0;
    for (int i = 0; i < CH; i++) {
        int idx = base + i;
        if (idx < N_NODES) local += cnt[idx];
    }
    sh[t] = local;
    __syncthreads();
    for (int o = 1; o < 1024; o <<= 1) {
        int v = 0;
        if (t >= o) v = sh[t - o];
        __syncthreads();
        if (t >= o) sh[t] += v;
        __syncthreads();
    }
    int run = (t == 0) ? 0 : sh[t - 1];
    for (int i = 0; i < CH; i++) {
        int idx = base + i;
        if (idx < N_NODES) {
            off[idx] = run;
            cur[idx] = run;
            run += cnt[idx];
        }
    }
    if (t == 0) off[N_NODES] = EAUG;
}

__global__ void csr_fill_k(const int* __restrict__ ei1, int* __restrict__ cur,
                           int* __restrict__ eid)
{
    int e = blockIdx.x * blockDim.x + threadIdx.x;
    if (e >= EAUG) return;
    int c = (e < N_EDGES) ? ei1[e] : (e - N_EDGES);
    int pos = atomicAdd(&cur[c], 1);
    eid[pos] = e;
}

// ---------------- per-node Wh dots -------------------------------------------
__global__ void pq_kernel(const float* __restrict__ G, const float* __restrict__ Wh,
                          float2* __restrict__ PQ)
{
    int node = (blockIdx.x * blockDim.x + threadIdx.x) >> 5;
    int lane = threadIdx.x & 31;
    if (node >= N_NODES) return;
    float4 xg = ((const float4*)(G + (size_t)node * 256))[lane];
    float4 a  = ((const float4*)Wh)[lane];
    float4 b  = ((const float4*)Wh)[lane + 32];
    float p = xg.x * a.x + xg.y * a.y + xg.z * a.z + xg.w * a.w;
    float q = xg.x * b.x + xg.y * b.y + xg.z * b.z + xg.w * b.w;
#pragma unroll
    for (int o = 16; o > 0; o >>= 1) {
        p += __shfl_xor_sync(0xffffffffu, p, o);
        q += __shfl_xor_sync(0xffffffffu, q, o);
    }
    if (lane == 0) PQ[node] = make_float2(p, q);
}

// ---------------- edge pass 1 -------------------------------------------------
__global__ void edge_pass1(const float* __restrict__ G,
                           const int* __restrict__ ei0, const int* __restrict__ ei1,
                           const float2* __restrict__ PQ, const float* __restrict__ bh,
                           float2* __restrict__ s_buf, float* __restrict__ Z)
{
    int gw   = (blockIdx.x * blockDim.x + threadIdx.x) >> 5;
    int lane = threadIdx.x & 31;
    if (gw >= EAUG) return;
    int r, c;
    if (gw < N_EDGES) { r = ei0[gw]; c = ei1[gw]; }
    else              { r = gw - N_EDGES; c = r; }

    float4 xr = ((const float4*)(G + (size_t)r * 256))[lane];
    float4 xc = ((const float4*)(G + (size_t)c * 256))[lane];

    float dx = xr.x - xc.x, dy = xr.y - xc.y, dz = xr.z - xc.z, dw = xr.w - xc.w;
    float ss = dx * dx + dy * dy + dz * dz + dw * dw;
#pragma unroll
    for (int o = 16; o > 0; o >>= 1)
        ss += __shfl_xor_sync(0xffffffffu, ss, o);
    if (lane == 0) {
        float g = sqrtf(ss + 1e-12f);
        float t = PQ[r].x + PQ[c].y + bh[0];
        float h = fmaxf(t, 0.f) + log1pf(__expf(-fabsf(t)));   // softplus
        float s = 1.f / (1.f + __expf(g + h));                 // sigmoid(-(g+h))
        float es = __expf(s);
        float ed = __expf(1.f - s);
        s_buf[gw] = make_float2(es, ed);
        atomicAdd(&Z[r],           es);
        atomicAdd(&Z[N_NODES + r], ed);
    }
}

// ---------------- aggregation of RAW input features -------------------------
__global__ void agg_k(const float* __restrict__ X,
                      const int* __restrict__ off, const int* __restrict__ eid,
                      const int* __restrict__ ei0,
                      const float2* __restrict__ s_buf, const float* __restrict__ invZ,
                      float* __restrict__ SC, float* __restrict__ SD)
{
    int node = (blockIdx.x * blockDim.x + threadIdx.x) >> 5;
    int lane = threadIdx.x & 31;
    if (node >= N_NODES) return;

    int p0 = off[node], p1 = off[node + 1];
    float4 ac = make_float4(0.f, 0.f, 0.f, 0.f);
    float4 ad = make_float4(0.f, 0.f, 0.f, 0.f);
    for (int p = p0; p < p1; p++) {
        int e = eid[p];
        int r = (e < N_EDGES) ? ei0[e] : (e - N_EDGES);
        float2 es = s_buf[e];
        float wc = es.x * invZ[r];
        float wd = es.y * invZ[N_NODES + r];
        float4 v = ((const float4*)(X + (size_t)r * 128))[lane];
        ac.x = fmaf(wc, v.x, ac.x); ac.y = fmaf(wc, v.y, ac.y);
        ac.z = fmaf(wc, v.z, ac.z); ac.w = fmaf(wc, v.w, ac.w);
        ad.x = fmaf(wd, v.x, ad.x); ad.y = fmaf(wd, v.y, ad.y);
        ad.z = fmaf(wd, v.z, ad.z); ad.w = fmaf(wd, v.w, ad.w);
    }
    ((float4*)(SC + (size_t)node * 128))[lane] = ac;
    ((float4*)(SD + (size_t)node * 128))[lane] = ad;
}

// ---------------- gate + combine + residual ----------------------------------
__global__ void gate_k(const float* __restrict__ OC, const float* __restrict__ OD,
                       const float* __restrict__ G,
                       const float* __restrict__ Wgate, const float* __restrict__ bgate,
                       const float* __restrict__ residual, float* __restrict__ out)
{
    int node = (blockIdx.x * blockDim.x + threadIdx.x) >> 5;
    int lane = threadIdx.x & 31;
    if (node >= N_NODES) return;

    float4 ac = ((const float4*)(OC + (size_t)node * 128))[lane];
    float4 ad = ((const float4*)(OD + (size_t)node * 128))[lane];
    float4 sf = ((const float4*)(G + (size_t)node * 256 + 128))[lane];

    float l[3];
#pragma unroll
    for (int k = 0; k < 3; k++) {
        float4 w0 = ((const float4*)(Wgate + k * 384))[lane];
        float4 w1 = ((const float4*)(Wgate + k * 384 + 128))[lane];
        float4 w2 = ((const float4*)(Wgate + k * 384 + 256))[lane];
        l[k] = w0.x * ac.x + w0.y * ac.y + w0.z * ac.z + w0.w * ac.w
             + w1.x * ad.x + w1.y * ad.y + w1.z * ad.z + w1.w * ad.w
             + w2.x * sf.x + w2.y * sf.y + w2.z * sf.z + w2.w * sf.w;
    }
#pragma unroll
    for (int o = 16; o > 0; o >>= 1) {
        l[0] += __shfl_xor_sync(0xffffffffu, l[0], o);
        l[1] += __shfl_xor_sync(0xffffffffu, l[1], o);
        l[2] += __shfl_xor_sync(0xffffffffu, l[2], o);
    }
    l[0] += bgate[0]; l[1] += bgate[1]; l[2] += bgate[2];
    float m  = fmaxf(l[0], fmaxf(l[1], l[2]));
    float e0 = __expf(l[0] - m), e1 = __expf(l[1] - m), e2 = __expf(l[2] - m);
    float inv = 1.f / (e0 + e1 + e2);
    float g0 = e0 * inv, g1 = e1 * inv, g2 = e2 * inv;

    float4 o4;
    o4.x = g0 * ac.x + g1 * ad.x + g2 * sf.x;
    o4.y = g0 * ac.y + g1 * ad.y + g2 * sf.y;
    o4.z = g0 * ac.z + g1 * ad.z + g2 * sf.z;
    o4.w = g0 * ac.w + g1 * ad.w + g2 * sf.w;
    if (residual) {
        float4 rv = ((const float4*)(residual + (size_t)node * 128))[lane];
        o4.x += rv.x; o4.y += rv.y; o4.z += rv.z; o4.w += rv.w;
    }
    ((float4*)(out + (size_t)node * 128))[lane] = o4;
}

// ---------------- launch ------------------------------------------------------
extern "C" void kernel_launch(void* const* d_in, const int* in_sizes, int n_in,
                              void* d_out, int out_size)
{
    (void)in_sizes; (void)n_in; (void)out_size;
    const float* x       = (const float*)d_in[0];
    const int*   ei      = (const int*)d_in[1];
    const float* mlp_W   = (const float*)d_in[2];
    const float* mlp_b   = (const float*)d_in[3];
    const float* mlp_g   = (const float*)d_in[4];
    const float* mlp_be  = (const float*)d_in[5];
    const float* bn0_g   = (const float*)d_in[6];
    const float* bn0_be  = (const float*)d_in[7];
    const float* cls_W   = (const float*)d_in[8];
    const float* cls_b   = (const float*)d_in[9];
    const float* Wg[2]    = {(const float*)d_in[10], (const float*)d_in[19]};
    const float* Wh[2]    = {(const float*)d_in[11], (const float*)d_in[20]};
    const float* bh[2]    = {(const float*)d_in[12], (const float*)d_in[21]};
    const float* Wcon[2]  = {(const float*)d_in[13], (const float*)d_in[22]};
    const float* Wdis[2]  = {(const float*)d_in[14], (const float*)d_in[23]};
    const float* Wself[2] = {(const float*)d_in[15], (const float*)d_in[24]};
    const float* bself[2] = {(const float*)d_in[16], (const float*)d_in[25]};
    const float* Wgate[2] = {(const float*)d_in[17], (const float*)d_in[26]};
    const float* bgate[2] = {(const float*)d_in[18], (const float*)d_in[27]};
    const int* ei0 = ei;
    const int* ei1 = ei + N_EDGES;
    float* out = (float*)d_out;

    float *pH0, *pX1, *pTmp, *pG, *pSC, *pSD, *pZ, *pStats;
    float2 *pS, *pPQ;
    int *pOff, *pCur, *pCnt, *pEid;
    cudaGetSymbolAddress((void**)&pH0,   d_h0);
    cudaGetSymbolAddress((void**)&pX1,   d_x1);
    cudaGetSymbolAddress((void**)&pTmp,  d_tmp);
    cudaGetSymbolAddress((void**)&pG,    d_G);
    cudaGetSymbolAddress((void**)&pSC,   d_SC);
    cudaGetSymbolAddress((void**)&pSD,   d_SD);
    cudaGetSymbolAddress((void**)&pPQ,   d_PQ);
    cudaGetSymbolAddress((void**)&pS,    d_s);
    cudaGetSymbolAddress((void**)&pZ,    d_Z);
    cudaGetSymbolAddress((void**)&pStats,d_stats);
    cudaGetSymbolAddress((void**)&pOff,  d_off);
    cudaGetSymbolAddress((void**)&pCur,  d_cur);
    cudaGetSymbolAddress((void**)&pCnt,  d_cnt);
    cudaGetSymbolAddress((void**)&pEid,  d_eid);

    cudaFuncSetAttribute(gemm_tc, cudaFuncAttributeMaxDynamicSharedMemorySize,
                         BSM_TOTAL);

    const int GR = (N_NODES + 127) / 128;          // 391 row blocks
    const int NODE_WARPS = (N_NODES * 32 + 255) / 256;

    // ---- fork: CSR build (independent of features) runs on side stream
    cudaEventRecord(g_ev[0], 0);
    cudaStreamWaitEvent(g_s1, g_ev[0], 0);
    init_counts_k<<<(N_NODES + 255) / 256, 256, 0, g_s1>>>(pCnt);
    hist_k<<<(N_EDGES + 255) / 256, 256, 0, g_s1>>>(ei1, pCnt);
    scan_k<<<1, 1024, 0, g_s1>>>(pCnt, pOff, pCur);
    csr_fill_k<<<(EAUG + 255) / 256, 256, 0, g_s1>>>(ei1, pCur, pEid);
    cudaEventRecord(g_ev[1], g_s1);

    // ---- MLP + BN + relu -> h0 (main stream, overlaps CSR build)
    {
        TJobs tj = {};
        tj.j[0] = {x, mlp_W, mlp_b, pTmp, 128, 0};
        tj.j[1] = tj.j[0];
        gemm_tc<<<dim3(GR, 1), 256, BSM_TOTAL>>>(tj, N_NODES);
    }
    zero_f<<<1, 256>>>(pStats, 256);
    bn_stats<<<(N_NODES + 63) / 64, 128>>>(pTmp, pStats);
    bn_apply<<<NODE_WARPS, 256>>>((const float4*)pTmp, pStats,
                                  mlp_g, mlp_be, nullptr, (float4*)pH0);

    // ---- conv layers
    const float* lin[2] = {pH0, pX1};
    for (int l = 0; l < 2; l++) {
        const float* X = lin[l];
        // fork: zero Z on side stream (prev consumer of Z already ordered here)
        cudaEventRecord(g_ev[2 + 2 * l], 0);
        cudaStreamWaitEvent(g_s1, g_ev[2 + 2 * l], 0);
        zero_f<<<(2 * N_NODES + 255) / 256, 256, 0, g_s1>>>(pZ, 2 * N_NODES);
        cudaEventRecord(g_ev[3 + 2 * l], g_s1);

        {   // G = [X@Wg.T | X@Wself.T + bself]
            TJobs tj = {};
            tj.j[0] = {X, Wg[l],    nullptr,  pG, 256, 0};
            tj.j[1] = {X, Wself[l], bself[l], pG, 256, 128};
            gemm_tc<<<dim3(GR, 2), 256, BSM_TOTAL>>>(tj, N_NODES);
        }
        pq_kernel<<<NODE_WARPS, 256>>>(pG, Wh[l], pPQ);
        cudaStreamWaitEvent(0, g_ev[3 + 2 * l], 0);   // Z zeroed
        edge_pass1<<<(EAUG * 32 + 255) / 256, 256>>>(pG, ei0, ei1, pPQ, bh[l],
                                                     pS, pZ);
        recip_f<<<(2 * N_NODES + 255) / 256, 256>>>(pZ, 2 * N_NODES);
        if (l == 0)
            cudaStreamWaitEvent(0, g_ev[1], 0);       // CSR ready
        agg_k<<<NODE_WARPS, 256>>>(X, pOff, pEid, ei0, pS, pZ, pSC, pSD);
        {   // SC = SC@Wcon.T, SD = SD@Wdis.T (in place; rows disjoint per CTA)
            TJobs tj = {};
            tj.j[0] = {pSC, Wcon[l], nullptr, pSC, 128, 0};
            tj.j[1] = {pSD, Wdis[l], nullptr, pSD, 128, 0};
            gemm_tc<<<dim3(GR, 2), 256, BSM_TOTAL>>>(tj, N_NODES);
        }
        gate_k<<<NODE_WARPS, 256>>>(pSC, pSD, pG, Wgate[l], bgate[l],
                                    (l == 0) ? nullptr : pX1, pTmp);
        if (l == 0) {
            zero_f<<<1, 256>>>(pStats, 256);
            bn_stats<<<(N_NODES + 63) / 64, 128>>>(pTmp, pStats);
            bn_apply<<<NODE_WARPS, 256>>>((const float4*)pTmp, pStats,
                                          bn0_g, bn0_be,
                                          (const float4*)pH0, (float4*)pX1);
        }
    }

    // ---- classifier: out = x2 @ cls_W.T + cls_b   (x2 lives in d_tmp)
    {
        GemmJobs gj = {};
        gj.j[0] = {pTmp, cls_W, cls_b, out, 40, 0, 40};
        gj.j[1] = gj.j[0];
        gemm_nt<<<dim3(GR, 1), 256>>>(gj, N_NODES);
    }
}

// round 16
// speedup vs baseline: 1.2539x; 1.1545x over previous
#include <cuda_runtime.h>
#include <cstdint>

#define N_NODES 50000
#define N_EDGES 800000
#define EAUG    (N_EDGES + N_NODES)
#define HID     128
#define NCLS    40

// ---------------- scratch (static device globals; no runtime alloc) --------
__device__ float  d_h0 [N_NODES * HID];
__device__ float  d_x1 [N_NODES * HID];
__device__ float  d_tmp[N_NODES * HID];
__device__ float  d_G  [(size_t)N_NODES * 256];   // [xg | xself]
__device__ float  d_SC [N_NODES * HID];
__device__ float  d_SD [N_NODES * HID];
__device__ float2 d_PQ [N_NODES];
__device__ float2 d_s  [EAUG];                    // {exp(s), exp(1-s)}
__device__ float  d_Z  [2 * N_NODES];
__device__ float  d_stats[2 * HID];
__device__ int    d_off [N_NODES + 1];
__device__ int    d_cur [N_NODES];
__device__ int    d_cnt [N_NODES];
__device__ int    d_eid [EAUG];

// ---------------- side stream + events (created once; no device memory) ----
static cudaStream_t g_s1;
static cudaEvent_t  g_ev[6];
struct SideStreamInit {
    SideStreamInit() {
        cudaStreamCreateWithFlags(&g_s1, cudaStreamNonBlocking);
        for (int i = 0; i < 6; i++)
            cudaEventCreateWithFlags(&g_ev[i], cudaEventDisableTiming);
    }
};
static SideStreamInit g_side_init;

// ============================================================================
// Tensor-core GEMM via mma.sync m16n8k16 bf16, 3-term split done at staging:
//   x = hi + lo;  hi = trunc-bf16(x) (top 16 bits, PRMT-packed);
//   lo = rn-bf16(x - hi).  D = Ah*Bh + Ah*Bl + Al*Bh  (lo*lo dropped ~2^-18).
// 128x128 tile, K=128 (A staged per 64-K chunk, B staged once), 8 warps 4x2.
// Smem word-strides % 32 == 4 -> conflict-free 32-bit fragment loads.
// ============================================================================
struct TJob {
    const float* A;
    const float* B;
    const float* bias;
    float*       C;
    int ldc;
    int coff;
};
struct TJobs { TJob j[2]; };

#define BA_STR 36   // uint32 words per A smem row (32 data + 4 pad)
#define BB_STR 68   // uint32 words per B smem row (64 data + 4 pad)
#define BSM_TOTAL ((2*128*BA_STR + 2*128*BB_STR) * 4)   // 106496 bytes

__device__ __forceinline__ uint32_t prmt_hi(uint32_t a, uint32_t b) {
    uint32_t d;
    asm("prmt.b32 %0, %1, %2, 0x7632;" : "=r"(d) : "r"(a), "r"(b));
    return d;   // {low16 = a[31:16], high16 = b[31:16]}
}
__device__ __forceinline__ uint32_t bf16x2_rn(float lo_e, float hi_e) {
    uint32_t d;   // low half = lo_e, high half = hi_e
    asm("cvt.rn.bf16x2.f32 %0, %1, %2;" : "=r"(d) : "f"(hi_e), "f"(lo_e));
    return d;
}
// split float4 (4 consecutive K elems) into 2 hi-words + 2 lo-words
__device__ __forceinline__ void split4(float4 v, uint32_t* hw, uint32_t* lw) {
    uint32_t ux = __float_as_uint(v.x), uy = __float_as_uint(v.y);
    uint32_t uz = __float_as_uint(v.z), uw = __float_as_uint(v.w);
    hw[0] = prmt_hi(ux, uy);
    hw[1] = prmt_hi(uz, uw);
    float lx = v.x - __uint_as_float(ux & 0xFFFF0000u);
    float ly = v.y - __uint_as_float(uy & 0xFFFF0000u);
    float lz = v.z - __uint_as_float(uz & 0xFFFF0000u);
    float lw_ = v.w - __uint_as_float(uw & 0xFFFF0000u);
    lw[0] = bf16x2_rn(lx, ly);
    lw[1] = bf16x2_rn(lz, lw_);
}

__device__ __forceinline__ void mma_bf16(float* d, const uint32_t* a,
                                         const uint32_t* b) {
    asm volatile(
        "mma.sync.aligned.m16n8k16.row.col.f32.bf16.bf16.f32 "
        "{%0,%1,%2,%3}, {%4,%5,%6,%7}, {%8,%9}, {%0,%1,%2,%3};"
        : "+f"(d[0]), "+f"(d[1]), "+f"(d[2]), "+f"(d[3])
        : "r"(a[0]), "r"(a[1]), "r"(a[2]), "r"(a[3]), "r"(b[0]), "r"(b[1]));
}

__global__ void __launch_bounds__(256, 2) gemm_tc(TJobs jobs, int nrows)
{
    extern __shared__ uint32_t smw[];
    uint32_t* Ah = smw;
    uint32_t* Al = smw + 128 * BA_STR;
    uint32_t* Bh = smw + 2 * 128 * BA_STR;
    uint32_t* Bl = Bh + 128 * BB_STR;

    const TJob job = jobs.j[blockIdx.y];
    const int row0 = blockIdx.x * 128;
    const int tid  = threadIdx.x;
    const int wid  = tid >> 5, lane = tid & 31;
    const int wm   = wid >> 1, wn = wid & 1;
    const int g    = lane >> 2, ti = lane & 3;

    // ---- stage + split B (128 x 128) once
#pragma unroll
    for (int i = 0; i < 16; i++) {
        int lin = tid + i * 256;
        int n   = lin >> 5;
        int kq  = (lin & 31) << 2;
        float4 v = *(const float4*)(job.B + (size_t)n * 128 + kq);
        uint32_t hw[2], lw[2];
        split4(v, hw, lw);
        int base = n * BB_STR + (kq >> 1);
        Bh[base] = hw[0]; Bh[base + 1] = hw[1];
        Bl[base] = lw[0]; Bl[base + 1] = lw[1];
    }

    float acc[2][8][4];
#pragma unroll
    for (int mt = 0; mt < 2; mt++)
#pragma unroll
        for (int nt = 0; nt < 8; nt++)
#pragma unroll
            for (int u = 0; u < 4; u++) acc[mt][nt][u] = 0.f;

    for (int c = 0; c < 2; c++) {
        // ---- stage + split A chunk (128 rows x 64 K)
#pragma unroll
        for (int i = 0; i < 8; i++) {
            int lin = tid + i * 256;
            int r   = lin >> 4;
            int kq  = (lin & 15) << 2;
            int grow = row0 + r;
            float4 v = make_float4(0.f, 0.f, 0.f, 0.f);
            if (grow < nrows)
                v = *(const float4*)(job.A + (size_t)grow * 128 + c * 64 + kq);
            uint32_t hw[2], lw[2];
            split4(v, hw, lw);
            int base = r * BA_STR + (kq >> 1);
            Ah[base] = hw[0]; Ah[base + 1] = hw[1];
            Al[base] = lw[0]; Al[base + 1] = lw[1];
        }
        __syncthreads();

#pragma unroll
        for (int s = 0; s < 4; s++) {           // k16 steps within 64-K chunk
            const int k0w = s * 8;              // word offset (2 bf16/word)
            uint32_t ah[2][4], al[2][4];
#pragma unroll
            for (int mt = 0; mt < 2; mt++) {
                int rb = wm * 32 + mt * 16;
                int i0 = (rb + g)     * BA_STR + k0w + ti;
                int i1 = (rb + g + 8) * BA_STR + k0w + ti;
                ah[mt][0] = Ah[i0];
                ah[mt][1] = Ah[i1];
                ah[mt][2] = Ah[i0 + 4];
                ah[mt][3] = Ah[i1 + 4];
                al[mt][0] = Al[i0];
                al[mt][1] = Al[i1];
                al[mt][2] = Al[i0 + 4];
                al[mt][3] = Al[i1 + 4];
            }
#pragma unroll
            for (int nt = 0; nt < 8; nt++) {
                int n = wn * 64 + nt * 8 + g;
                int b0 = n * BB_STR + c * 32 + k0w + ti;
                uint32_t bh[2], bl[2];
                bh[0] = Bh[b0]; bh[1] = Bh[b0 + 4];
                bl[0] = Bl[b0]; bl[1] = Bl[b0 + 4];
#pragma unroll
                for (int mt = 0; mt < 2; mt++) {
                    mma_bf16(acc[mt][nt], ah[mt], bh);
                    mma_bf16(acc[mt][nt], ah[mt], bl);
                    mma_bf16(acc[mt][nt], al[mt], bh);
                }
            }
        }
        __syncthreads();
    }

    // ---- epilogue
#pragma unroll
    for (int mt = 0; mt < 2; mt++) {
#pragma unroll
        for (int h = 0; h < 2; h++) {
            int grow = row0 + wm * 32 + mt * 16 + g + h * 8;
            if (grow >= nrows) continue;
            float* cp = job.C + (size_t)grow * job.ldc + job.coff + wn * 64;
#pragma unroll
            for (int nt = 0; nt < 8; nt++) {
                int col = nt * 8 + 2 * ti;
                float vx = acc[mt][nt][2 * h];
                float vy = acc[mt][nt][2 * h + 1];
                if (job.bias) {
                    vx += job.bias[wn * 64 + col];
                    vy += job.bias[wn * 64 + col + 1];
                }
                *(float2*)(cp + col) = make_float2(vx, vy);
            }
        }
    }
}

// ---------------- scalar GEMM (classifier only, ncols=40) -------------------
struct GemmJob {
    const float* A;
    const float* B;
    const float* bias;
    float*       C;
    int ldc;
    int coff;
    int ncols;
};
struct GemmJobs { GemmJob j[2]; };

__device__ __forceinline__ void fma2(unsigned long long& d,
                                     unsigned long long a, unsigned long long b) {
    asm("fma.rn.f32x2 %0, %1, %2, %0;" : "+l"(d) : "l"(a), "l"(b));
}
__device__ __forceinline__ void unpack2(unsigned long long v, float& lo, float& hi) {
    asm("mov.b64 {%0, %1}, %2;" : "=f"(lo), "=f"(hi) : "l"(v));
}

#define AS_STRIDE 260
#define BS_STRIDE 144

__global__ void __launch_bounds__(256, 2) gemm_nt(
    GemmJobs jobs, int nrows)
{
    const GemmJob job = jobs.j[blockIdx.y];
    const float* __restrict__ A    = job.A;
    const float* __restrict__ B    = job.B;
    const float* __restrict__ bias = job.bias;
    const int ncols = job.ncols;
    const int row0  = blockIdx.x * 128;

    __shared__ float As[16][AS_STRIDE];
    __shared__ float Bs[16][BS_STRIDE];

    const int t  = threadIdx.x;
    const int tx = t & 15;
    const int ty = t >> 4;

    unsigned long long acc[8][4];
#pragma unroll
    for (int y = 0; y < 8; y++)
#pragma unroll
        for (int xp = 0; xp < 4; xp++) acc[y][xp] = 0ULL;

    const int b_base = tx * 8 + ((tx >> 2) << 2);

    for (int k0 = 0; k0 < 128; k0 += 16) {
#pragma unroll
        for (int i = 0; i < 2; i++) {
            int lin = t + i * 256;
            int r   = lin >> 2;
            int kq  = lin & 3;
            float4 v = make_float4(0.f, 0.f, 0.f, 0.f);
            int grow = row0 + r;
            if (grow < nrows)
                v = *(const float4*)(A + (size_t)grow * 128 + k0 + kq * 4);
            *(float2*)&As[kq * 4 + 0][2 * r] = make_float2(v.x, v.x);
            *(float2*)&As[kq * 4 + 1][2 * r] = make_float2(v.y, v.y);
            *(float2*)&As[kq * 4 + 2][2 * r] = make_float2(v.z, v.z);
            *(float2*)&As[kq * 4 + 3][2 * r] = make_float2(v.w, v.w);
        }
#pragma unroll
        for (int i = 0; i < 2; i++) {
            int lin = t + i * 256;
            int j   = lin >> 2;
            int kq  = lin & 3;
            float4 v = make_float4(0.f, 0.f, 0.f, 0.f);
            if (j < ncols)
                v = *(const float4*)(B + (size_t)j * 128 + k0 + kq * 4);
            int pj = j + ((j >> 5) << 2);
            Bs[kq * 4 + 0][pj] = v.x;
            Bs[kq * 4 + 1][pj] = v.y;
            Bs[kq * 4 + 2][pj] = v.z;
            Bs[kq * 4 + 3][pj] = v.w;
        }
        __syncthreads();
#pragma unroll
        for (int kk = 0; kk < 16; kk++) {
            unsigned long long ad[8], bp[4];
            const ulonglong2* ap = (const ulonglong2*)&As[kk][ty * 16];
            const ulonglong2* bq = (const ulonglong2*)&Bs[kk][b_base];
#pragma unroll
            for (int i = 0; i < 4; i++) {
                ulonglong2 u = ap[i];
                ad[2 * i]     = u.x;
                ad[2 * i + 1] = u.y;
            }
#pragma unroll
            for (int i = 0; i < 2; i++) {
                ulonglong2 u = bq[i];
                bp[2 * i]     = u.x;
                bp[2 * i + 1] = u.y;
            }
#pragma unroll
            for (int y = 0; y < 8; y++)
#pragma unroll
                for (int xp = 0; xp < 4; xp++)
                    fma2(acc[y][xp], ad[y], bp[xp]);
        }
        __syncthreads();
    }

#pragma unroll
    for (int y = 0; y < 8; y++) {
        int grow = row0 + ty * 8 + y;
        if (grow >= nrows) continue;
        float* cp = job.C + (size_t)grow * job.ldc + job.coff;
        float c[8];
#pragma unroll
        for (int xp = 0; xp < 4; xp++)
            unpack2(acc[y][xp], c[2 * xp], c[2 * xp + 1]);
#pragma unroll
        for (int xq = 0; xq < 2; xq++) {
            int col = tx * 8 + xq * 4;
            if (col >= ncols) continue;
            float4 v = make_float4(c[xq * 4 + 0], c[xq * 4 + 1],
                                   c[xq * 4 + 2], c[xq * 4 + 3]);
            if (bias) {
                v.x += bias[col + 0];
                v.y += bias[col + 1];
                v.z += bias[col + 2];
                v.w += bias[col + 3];
            }
            *(float4*)(cp + col) = v;
        }
    }
}

// ---------------- BatchNorm --------------------------------------------------
__global__ void bn_stats(const float* __restrict__ X, float* __restrict__ stats)
{
    int c  = threadIdx.x;
    int r0 = blockIdx.x * 64;
    int r1 = min(r0 + 64, N_NODES);
    float s = 0.f, q = 0.f;
    for (int r = r0; r < r1; r++) {
        float v = X[(size_t)r * 128 + c];
        s += v;
        q = fmaf(v, v, q);
    }
    atomicAdd(&stats[c], s);
    atomicAdd(&stats[128 + c], q);
}

__global__ void bn_apply(const float4* __restrict__ X, const float* __restrict__ stats,
                         const float* __restrict__ gamma, const float* __restrict__ beta,
                         const float4* __restrict__ residual, float4* __restrict__ out)
{
    int i = blockIdx.x * blockDim.x + threadIdx.x;
    if (i >= N_NODES * 32) return;
    int c0 = (i & 31) * 4;
    const float invN = 1.f / (float)N_NODES;
    float4 v = X[i];
    float r[4] = {v.x, v.y, v.z, v.w};
#pragma unroll
    for (int k = 0; k < 4; k++) {
        int c = c0 + k;
        float m   = stats[c] * invN;
        float var = stats[128 + c] * invN - m * m;
        float u = gamma[c] * (r[k] - m) * rsqrtf(var + 1e-5f) + beta[c];
        r[k] = fmaxf(u, 0.f);
    }
    float4 o = make_float4(r[0], r[1], r[2], r[3]);
    if (residual) {
        float4 rv = residual[i];
        o.x += rv.x; o.y += rv.y; o.z += rv.z; o.w += rv.w;
    }
    out[i] = o;
}

// ---------------- small utility kernels -------------------------------------
__global__ void zero_f(float* __restrict__ p, int n)
{
    int i = blockIdx.x * blockDim.x + threadIdx.x;
    if (i < n) p[i] = 0.f;
}

__global__ void recip_f(float* __restrict__ p, int n)
{
    int i = blockIdx.x * blockDim.x + threadIdx.x;
    if (i < n) p[i] = 1.f / p[i];
}

__global__ void init_counts_k(int* __restrict__ cnt)
{
    int i = blockIdx.x * blockDim.x + threadIdx.x;
    if (i < N_NODES) cnt[i] = 1;   // self loop
}

__global__ void hist_k(const int* __restrict__ ei1, int* __restrict__ cnt)
{
    int e = blockIdx.x * blockDim.x + threadIdx.x;
    if (e < N_EDGES) atomicAdd(&cnt[ei1[e]], 1);
}

__global__ void scan_k(const int* __restrict__ cnt, int* __restrict__ off,
                       int* __restrict__ cur)
{
    __shared__ int sh[1024];
    const int CH = (N_NODES + 1023) / 1024;
    int t = threadIdx.x;
    int base = t * CH;
    int local = 0;
    for (int i = 0; i < CH; i++) {
        int idx = base + i;
        if (idx < N_NODES) local += cnt[idx];
    }
    sh[t] = local;
    __syncthreads();
    for (int o = 1; o < 1024; o <<= 1) {
        int v = 0;
        if (t >= o) v = sh[t - o];
        __syncthreads();
        if (t >= o) sh[t] += v;
        __syncthreads();
    }
    int run = (t == 0) ? 0 : sh[t - 1];
    for (int i = 0; i < CH; i++) {
        int idx = base + i;
        if (idx < N_NODES) {
            off[idx] = run;
            cur[idx] = run;
            run += cnt[idx];
        }
    }
    if (t == 0) off[N_NODES] = EAUG;
}

__global__ void csr_fill_k(const int* __restrict__ ei1, int* __restrict__ cur,
                           int* __restrict__ eid)
{
    int e = blockIdx.x * blockDim.x + threadIdx.x;
    if (e >= EAUG) return;
    int c = (e < N_EDGES) ? ei1[e] : (e - N_EDGES);
    int pos = atomicAdd(&cur[c], 1);
    eid[pos] = e;
}

// ---------------- per-node Wh dots -------------------------------------------
__global__ void pq_kernel(const float* __restrict__ G, const float* __restrict__ Wh,
                          float2* __restrict__ PQ)
{
    int node = (blockIdx.x * blockDim.x + threadIdx.x) >> 5;
    int lane = threadIdx.x & 31;
    if (node >= N_NODES) return;
    float4 xg = ((const float4*)(G + (size_t)node * 256))[lane];
    float4 a  = ((const float4*)Wh)[lane];
    float4 b  = ((const float4*)Wh)[lane + 32];
    float p = xg.x * a.x + xg.y * a.y + xg.z * a.z + xg.w * a.w;
    float q = xg.x * b.x + xg.y * b.y + xg.z * b.z + xg.w * b.w;
#pragma unroll
    for (int o = 16; o > 0; o >>= 1) {
        p += __shfl_xor_sync(0xffffffffu, p, o);
        q += __shfl_xor_sync(0xffffffffu, q, o);
    }
    if (lane == 0) PQ[node] = make_float2(p, q);
}

// ---------------- edge pass 1: TWO edges per warp, full 32-lane rows ---------
// Both edges' squared-distance sums reduce in the same butterfly; scalar
// tails run in parallel on lane 0 (edge0) and lane 16 (edge1).
__global__ void edge_pass1(const float* __restrict__ G,
                           const int* __restrict__ ei0, const int* __restrict__ ei1,
                           const float2* __restrict__ PQ, const float* __restrict__ bh,
                           float2* __restrict__ s_buf, float* __restrict__ Z)
{
    int warp = (blockIdx.x * blockDim.x + threadIdx.x) >> 5;
    int lane = threadIdx.x & 31;
    int e0 = 2 * warp;
    int e1 = 2 * warp + 1;
    if (e0 >= EAUG) return;   // EAUG is even; e1 valid whenever e0 is

    int r0, c0, r1, c1;
    if (e0 < N_EDGES) { r0 = ei0[e0]; c0 = ei1[e0]; }
    else              { r0 = e0 - N_EDGES; c0 = r0; }
    if (e1 < N_EDGES) { r1 = ei0[e1]; c1 = ei1[e1]; }
    else              { r1 = e1 - N_EDGES; c1 = r1; }

    float4 xr0 = ((const float4*)(G + (size_t)r0 * 256))[lane];
    float4 xc0 = ((const float4*)(G + (size_t)c0 * 256))[lane];
    float4 xr1 = ((const float4*)(G + (size_t)r1 * 256))[lane];
    float4 xc1 = ((const float4*)(G + (size_t)c1 * 256))[lane];

    float dx = xr0.x - xc0.x, dy = xr0.y - xc0.y;
    float dz = xr0.z - xc0.z, dw = xr0.w - xc0.w;
    float ss0 = dx * dx + dy * dy + dz * dz + dw * dw;
    dx = xr1.x - xc1.x; dy = xr1.y - xc1.y;
    dz = xr1.z - xc1.z; dw = xr1.w - xc1.w;
    float ss1 = dx * dx + dy * dy + dz * dz + dw * dw;
#pragma unroll
    for (int o = 16; o > 0; o >>= 1) {
        ss0 += __shfl_xor_sync(0xffffffffu, ss0, o);
        ss1 += __shfl_xor_sync(0xffffffffu, ss1, o);
    }
    if (lane == 0 || lane == 16) {
        float ss = (lane == 0) ? ss0 : ss1;
        int   e  = (lane == 0) ? e0  : e1;
        int   r  = (lane == 0) ? r0  : r1;
        int   c  = (lane == 0) ? c0  : c1;
        float g = sqrtf(ss + 1e-12f);
        float t = PQ[r].x + PQ[c].y + bh[0];
        float h = fmaxf(t, 0.f) + log1pf(__expf(-fabsf(t)));   // softplus
        float s = 1.f / (1.f + __expf(g + h));                 // sigmoid(-(g+h))
        float es = __expf(s);
        float ed = __expf(1.f - s);
        s_buf[e] = make_float2(es, ed);
        atomicAdd(&Z[r],           es);
        atomicAdd(&Z[N_NODES + r], ed);
    }
}

// ---------------- aggregation of RAW input features -------------------------
__global__ void agg_k(const float* __restrict__ X,
                      const int* __restrict__ off, const int* __restrict__ eid,
                      const int* __restrict__ ei0,
                      const float2* __restrict__ s_buf, const float* __restrict__ invZ,
                      float* __restrict__ SC, float* __restrict__ SD)
{
    int node = (blockIdx.x * blockDim.x + threadIdx.x) >> 5;
    int lane = threadIdx.x & 31;
    if (node >= N_NODES) return;

    int p0 = off[node], p1 = off[node + 1];
    float4 ac = make_float4(0.f, 0.f, 0.f, 0.f);
    float4 ad = make_float4(0.f, 0.f, 0.f, 0.f);
    for (int p = p0; p < p1; p++) {
        int e = eid[p];
        int r = (e < N_EDGES) ? ei0[e] : (e - N_EDGES);
        float2 es = s_buf[e];
        float wc = es.x * invZ[r];
        float wd = es.y * invZ[N_NODES + r];
        float4 v = ((const float4*)(X + (size_t)r * 128))[lane];
        ac.x = fmaf(wc, v.x, ac.x); ac.y = fmaf(wc, v.y, ac.y);
        ac.z = fmaf(wc, v.z, ac.z); ac.w = fmaf(wc, v.w, ac.w);
        ad.x = fmaf(wd, v.x, ad.x); ad.y = fmaf(wd, v.y, ad.y);
        ad.z = fmaf(wd, v.z, ad.z); ad.w = fmaf(wd, v.w, ad.w);
    }
    ((float4*)(SC + (size_t)node * 128))[lane] = ac;
    ((float4*)(SD + (size_t)node * 128))[lane] = ad;
}

// ---------------- gate + combine + residual ----------------------------------
__global__ void gate_k(const float* __restrict__ OC, const float* __restrict__ OD,
                       const float* __restrict__ G,
                       const float* __restrict__ Wgate, const float* __restrict__ bgate,
                       const float* __restrict__ residual, float* __restrict__ out)
{
    int node = (blockIdx.x * blockDim.x + threadIdx.x) >> 5;
    int lane = threadIdx.x & 31;
    if (node >= N_NODES) return;

    float4 ac = ((const float4*)(OC + (size_t)node * 128))[lane];
    float4 ad = ((const float4*)(OD + (size_t)node * 128))[lane];
    float4 sf = ((const float4*)(G + (size_t)node * 256 + 128))[lane];

    float l[3];
#pragma unroll
    for (int k = 0; k < 3; k++) {
        float4 w0 = ((const float4*)(Wgate + k * 384))[lane];
        float4 w1 = ((const float4*)(Wgate + k * 384 + 128))[lane];
        float4 w2 = ((const float4*)(Wgate + k * 384 + 256))[lane];
        l[k] = w0.x * ac.x + w0.y * ac.y + w0.z * ac.z + w0.w * ac.w
             + w1.x * ad.x + w1.y * ad.y + w1.z * ad.z + w1.w * ad.w
             + w2.x * sf.x + w2.y * sf.y + w2.z * sf.z + w2.w * sf.w;
    }
#pragma unroll
    for (int o = 16; o > 0; o >>= 1) {
        l[0] += __shfl_xor_sync(0xffffffffu, l[0], o);
        l[1] += __shfl_xor_sync(0xffffffffu, l[1], o);
        l[2] += __shfl_xor_sync(0xffffffffu, l[2], o);
    }
    l[0] += bgate[0]; l[1] += bgate[1]; l[2] += bgate[2];
    float m  = fmaxf(l[0], fmaxf(l[1], l[2]));
    float e0 = __expf(l[0] - m), e1 = __expf(l[1] - m), e2 = __expf(l[2] - m);
    float inv = 1.f / (e0 + e1 + e2);
    float g0 = e0 * inv, g1 = e1 * inv, g2 = e2 * inv;

    float4 o4;
    o4.x = g0 * ac.x + g1 * ad.x + g2 * sf.x;
    o4.y = g0 * ac.y + g1 * ad.y + g2 * sf.y;
    o4.z = g0 * ac.z + g1 * ad.z + g2 * sf.z;
    o4.w = g0 * ac.w + g1 * ad.w + g2 * sf.w;
    if (residual) {
        float4 rv = ((const float4*)(residual + (size_t)node * 128))[lane];
        o4.x += rv.x; o4.y += rv.y; o4.z += rv.z; o4.w += rv.w;
    }
    ((float4*)(out + (size_t)node * 128))[lane] = o4;
}

// ---------------- launch ------------------------------------------------------
extern "C" void kernel_launch(void* const* d_in, const int* in_sizes, int n_in,
                              void* d_out, int out_size)
{
    (void)in_sizes; (void)n_in; (void)out_size;
    const float* x       = (const float*)d_in[0];
    const int*   ei      = (const int*)d_in[1];
    const float* mlp_W   = (const float*)d_in[2];
    const float* mlp_b   = (const float*)d_in[3];
    const float* mlp_g   = (const float*)d_in[4];
    const float* mlp_be  = (const float*)d_in[5];
    const float* bn0_g   = (const float*)d_in[6];
    const float* bn0_be  = (const float*)d_in[7];
    const float* cls_W   = (const float*)d_in[8];
    const float* cls_b   = (const float*)d_in[9];
    const float* Wg[2]    = {(const float*)d_in[10], (const float*)d_in[19]};
    const float* Wh[2]    = {(const float*)d_in[11], (const float*)d_in[20]};
    const float* bh[2]    = {(const float*)d_in[12], (const float*)d_in[21]};
    const float* Wcon[2]  = {(const float*)d_in[13], (const float*)d_in[22]};
    const float* Wdis[2]  = {(const float*)d_in[14], (const float*)d_in[23]};
    const float* Wself[2] = {(const float*)d_in[15], (const float*)d_in[24]};
    const float* bself[2] = {(const float*)d_in[16], (const float*)d_in[25]};
    const float* Wgate[2] = {(const float*)d_in[17], (const float*)d_in[26]};
    const float* bgate[2] = {(const float*)d_in[18], (const float*)d_in[27]};
    const int* ei0 = ei;
    const int* ei1 = ei + N_EDGES;
    float* out = (float*)d_out;

    float *pH0, *pX1, *pTmp, *pG, *pSC, *pSD, *pZ, *pStats;
    float2 *pS, *pPQ;
    int *pOff, *pCur, *pCnt, *pEid;
    cudaGetSymbolAddress((void**)&pH0,   d_h0);
    cudaGetSymbolAddress((void**)&pX1,   d_x1);
    cudaGetSymbolAddress((void**)&pTmp,  d_tmp);
    cudaGetSymbolAddress((void**)&pG,    d_G);
    cudaGetSymbolAddress((void**)&pSC,   d_SC);
    cudaGetSymbolAddress((void**)&pSD,   d_SD);
    cudaGetSymbolAddress((void**)&pPQ,   d_PQ);
    cudaGetSymbolAddress((void**)&pS,    d_s);
    cudaGetSymbolAddress((void**)&pZ,    d_Z);
    cudaGetSymbolAddress((void**)&pStats,d_stats);
    cudaGetSymbolAddress((void**)&pOff,  d_off);
    cudaGetSymbolAddress((void**)&pCur,  d_cur);
    cudaGetSymbolAddress((void**)&pCnt,  d_cnt);
    cudaGetSymbolAddress((void**)&pEid,  d_eid);

    cudaFuncSetAttribute(gemm_tc, cudaFuncAttributeMaxDynamicSharedMemorySize,
                         BSM_TOTAL);

    const int GR = (N_NODES + 127) / 128;          // 391 row blocks
    const int NODE_WARPS = (N_NODES * 32 + 255) / 256;
    const int EDGE_WARPS = ((EAUG / 2) * 32 + 255) / 256;

    // ---- fork: CSR build (independent of features) runs on side stream
    cudaEventRecord(g_ev[0], 0);
    cudaStreamWaitEvent(g_s1, g_ev[0], 0);
    init_counts_k<<<(N_NODES + 255) / 256, 256, 0, g_s1>>>(pCnt);
    hist_k<<<(N_EDGES + 255) / 256, 256, 0, g_s1>>>(ei1, pCnt);
    scan_k<<<1, 1024, 0, g_s1>>>(pCnt, pOff, pCur);
    csr_fill_k<<<(EAUG + 255) / 256, 256, 0, g_s1>>>(ei1, pCur, pEid);
    cudaEventRecord(g_ev[1], g_s1);

    // ---- MLP + BN + relu -> h0 (main stream, overlaps CSR build)
    {
        TJobs tj = {};
        tj.j[0] = {x, mlp_W, mlp_b, pTmp, 128, 0};
        tj.j[1] = tj.j[0];
        gemm_tc<<<dim3(GR, 1), 256, BSM_TOTAL>>>(tj, N_NODES);
    }
    zero_f<<<1, 256>>>(pStats, 256);
    bn_stats<<<(N_NODES + 63) / 64, 128>>>(pTmp, pStats);
    bn_apply<<<NODE_WARPS, 256>>>((const float4*)pTmp, pStats,
                                  mlp_g, mlp_be, nullptr, (float4*)pH0);

    // ---- conv layers
    const float* lin[2] = {pH0, pX1};
    for (int l = 0; l < 2; l++) {
        const float* X = lin[l];
        // fork: zero Z on side stream (prev consumer of Z already ordered here)
        cudaEventRecord(g_ev[2 + 2 * l], 0);
        cudaStreamWaitEvent(g_s1, g_ev[2 + 2 * l], 0);
        zero_f<<<(2 * N_NODES + 255) / 256, 256, 0, g_s1>>>(pZ, 2 * N_NODES);
        cudaEventRecord(g_ev[3 + 2 * l], g_s1);

        {   // G = [X@Wg.T | X@Wself.T + bself]
            TJobs tj = {};
            tj.j[0] = {X, Wg[l],    nullptr,  pG, 256, 0};
            tj.j[1] = {X, Wself[l], bself[l], pG, 256, 128};
            gemm_tc<<<dim3(GR, 2), 256, BSM_TOTAL>>>(tj, N_NODES);
        }
        pq_kernel<<<NODE_WARPS, 256>>>(pG, Wh[l], pPQ);
        cudaStreamWaitEvent(0, g_ev[3 + 2 * l], 0);   // Z zeroed
        edge_pass1<<<EDGE_WARPS, 256>>>(pG, ei0, ei1, pPQ, bh[l], pS, pZ);
        recip_f<<<(2 * N_NODES + 255) / 256, 256>>>(pZ, 2 * N_NODES);
        if (l == 0)
            cudaStreamWaitEvent(0, g_ev[1], 0);       // CSR ready
        agg_k<<<NODE_WARPS, 256>>>(X, pOff, pEid, ei0, pS, pZ, pSC, pSD);
        {   // SC = SC@Wcon.T, SD = SD@Wdis.T (in place; rows disjoint per CTA)
            TJobs tj = {};
            tj.j[0] = {pSC, Wcon[l], nullptr, pSC, 128, 0};
            tj.j[1] = {pSD, Wdis[l], nullptr, pSD, 128, 0};
            gemm_tc<<<dim3(GR, 2), 256, BSM_TOTAL>>>(tj, N_NODES);
        }
        gate_k<<<NODE_WARPS, 256>>>(pSC, pSD, pG, Wgate[l], bgate[l],
                                    (l == 0) ? nullptr : pX1, pTmp);
        if (l == 0) {
            zero_f<<<1, 256>>>(pStats, 256);
            bn_stats<<<(N_NODES + 63) / 64, 128>>>(pTmp, pStats);
            bn_apply<<<NODE_WARPS, 256>>>((const float4*)pTmp, pStats,
                                          bn0_g, bn0_be,
                                          (const float4*)pH0, (float4*)pX1);
        }
    }

    // ---- classifier: out = x2 @ cls_W.T + cls_b   (x2 lives in d_tmp)
    {
        GemmJobs gj = {};
        gj.j[0] = {pTmp, cls_W, cls_b, out, 40, 0, 40};
        gj.j[1] = gj.j[0];
        gemm_nt<<<dim3(GR, 1), 256>>>(gj, N_NODES);
    }
}

// round 17
// speedup vs baseline: 1.2608x; 1.0055x over previous
#include <cuda_runtime.h>
#include <cstdint>

#define N_NODES 50000
#define N_EDGES 800000
#define EAUG    (N_EDGES + N_NODES)
#define HID     128
#define NCLS    40

// ---------------- scratch (static device globals; no runtime alloc) --------
__device__ float  d_h0 [N_NODES * HID];
__device__ float  d_x1 [N_NODES * HID];
__device__ float  d_tmp[N_NODES * HID];
__device__ float  d_G  [(size_t)N_NODES * 256];   // [xg | xself]
__device__ float  d_SC [N_NODES * HID];
__device__ float  d_SD [N_NODES * HID];
__device__ float2 d_PQ [N_NODES];
__device__ float2 d_s  [EAUG];                    // {exp(s), exp(1-s)}
__device__ float  d_Z  [2 * N_NODES];
__device__ float  d_stats[2 * HID];
__device__ int    d_off [N_NODES + 1];
__device__ int    d_cur [N_NODES];
__device__ int    d_cnt [N_NODES];
__device__ int    d_eid [EAUG];

// ---------------- side stream + events (created once; no device memory) ----
static cudaStream_t g_s1;
static cudaEvent_t  g_ev[6];
struct SideStreamInit {
    SideStreamInit() {
        cudaStreamCreateWithFlags(&g_s1, cudaStreamNonBlocking);
        for (int i = 0; i < 6; i++)
            cudaEventCreateWithFlags(&g_ev[i], cudaEventDisableTiming);
    }
};
static SideStreamInit g_side_init;

// ============================================================================
// Tensor-core GEMM via mma.sync m16n8k16 bf16, 3-term split done at staging:
//   x = hi + lo;  hi = trunc-bf16(x) (top 16 bits, PRMT-packed);
//   lo = rn-bf16(x - hi).  D = Ah*Bh + Ah*Bl + Al*Bh  (lo*lo dropped ~2^-18).
// 128x128 tile, K=128 (A staged per 64-K chunk, B staged once), 8 warps 4x2.
// Smem word-strides % 32 == 4 -> conflict-free 32-bit fragment loads.
// ============================================================================
struct TJob {
    const float* A;
    const float* B;
    const float* bias;
    float*       C;
    int ldc;
    int coff;
};
struct TJobs { TJob j[2]; };

#define BA_STR 36   // uint32 words per A smem row (32 data + 4 pad)
#define BB_STR 68   // uint32 words per B smem row (64 data + 4 pad)
#define BSM_TOTAL ((2*128*BA_STR + 2*128*BB_STR) * 4)   // 106496 bytes

__device__ __forceinline__ uint32_t prmt_hi(uint32_t a, uint32_t b) {
    uint32_t d;
    asm("prmt.b32 %0, %1, %2, 0x7632;" : "=r"(d) : "r"(a), "r"(b));
    return d;   // {low16 = a[31:16], high16 = b[31:16]}
}
__device__ __forceinline__ uint32_t bf16x2_rn(float lo_e, float hi_e) {
    uint32_t d;   // low half = lo_e, high half = hi_e
    asm("cvt.rn.bf16x2.f32 %0, %1, %2;" : "=r"(d) : "f"(hi_e), "f"(lo_e));
    return d;
}
// split float4 (4 consecutive K elems) into 2 hi-words + 2 lo-words
__device__ __forceinline__ void split4(float4 v, uint32_t* hw, uint32_t* lw) {
    uint32_t ux = __float_as_uint(v.x), uy = __float_as_uint(v.y);
    uint32_t uz = __float_as_uint(v.z), uw = __float_as_uint(v.w);
    hw[0] = prmt_hi(ux, uy);
    hw[1] = prmt_hi(uz, uw);
    float lx = v.x - __uint_as_float(ux & 0xFFFF0000u);
    float ly = v.y - __uint_as_float(uy & 0xFFFF0000u);
    float lz = v.z - __uint_as_float(uz & 0xFFFF0000u);
    float lw_ = v.w - __uint_as_float(uw & 0xFFFF0000u);
    lw[0] = bf16x2_rn(lx, ly);
    lw[1] = bf16x2_rn(lz, lw_);
}

__device__ __forceinline__ void mma_bf16(float* d, const uint32_t* a,
                                         const uint32_t* b) {
    asm volatile(
        "mma.sync.aligned.m16n8k16.row.col.f32.bf16.bf16.f32 "
        "{%0,%1,%2,%3}, {%4,%5,%6,%7}, {%8,%9}, {%0,%1,%2,%3};"
        : "+f"(d[0]), "+f"(d[1]), "+f"(d[2]), "+f"(d[3])
        : "r"(a[0]), "r"(a[1]), "r"(a[2]), "r"(a[3]), "r"(b[0]), "r"(b[1]));
}

__global__ void __launch_bounds__(256, 2) gemm_tc(TJobs jobs, int nrows)
{
    extern __shared__ uint32_t smw[];
    uint32_t* Ah = smw;
    uint32_t* Al = smw + 128 * BA_STR;
    uint32_t* Bh = smw + 2 * 128 * BA_STR;
    uint32_t* Bl = Bh + 128 * BB_STR;

    const TJob job = jobs.j[blockIdx.y];
    const int row0 = blockIdx.x * 128;
    const int tid  = threadIdx.x;
    const int wid  = tid >> 5, lane = tid & 31;
    const int wm   = wid >> 1, wn = wid & 1;
    const int g    = lane >> 2, ti = lane & 3;

    // ---- stage + split B (128 x 128) once
#pragma unroll
    for (int i = 0; i < 16; i++) {
        int lin = tid + i * 256;
        int n   = lin >> 5;
        int kq  = (lin & 31) << 2;
        float4 v = *(const float4*)(job.B + (size_t)n * 128 + kq);
        uint32_t hw[2], lw[2];
        split4(v, hw, lw);
        int base = n * BB_STR + (kq >> 1);
        Bh[base] = hw[0]; Bh[base + 1] = hw[1];
        Bl[base] = lw[0]; Bl[base + 1] = lw[1];
    }

    float acc[2][8][4];
#pragma unroll
    for (int mt = 0; mt < 2; mt++)
#pragma unroll
        for (int nt = 0; nt < 8; nt++)
#pragma unroll
            for (int u = 0; u < 4; u++) acc[mt][nt][u] = 0.f;

    for (int c = 0; c < 2; c++) {
        // ---- stage + split A chunk (128 rows x 64 K)
#pragma unroll
        for (int i = 0; i < 8; i++) {
            int lin = tid + i * 256;
            int r   = lin >> 4;
            int kq  = (lin & 15) << 2;
            int grow = row0 + r;
            float4 v = make_float4(0.f, 0.f, 0.f, 0.f);
            if (grow < nrows)
                v = *(const float4*)(job.A + (size_t)grow * 128 + c * 64 + kq);
            uint32_t hw[2], lw[2];
            split4(v, hw, lw);
            int base = r * BA_STR + (kq >> 1);
            Ah[base] = hw[0]; Ah[base + 1] = hw[1];
            Al[base] = lw[0]; Al[base + 1] = lw[1];
        }
        __syncthreads();

#pragma unroll
        for (int s = 0; s < 4; s++) {           // k16 steps within 64-K chunk
            const int k0w = s * 8;              // word offset (2 bf16/word)
            uint32_t ah[2][4], al[2][4];
#pragma unroll
            for (int mt = 0; mt < 2; mt++) {
                int rb = wm * 32 + mt * 16;
                int i0 = (rb + g)     * BA_STR + k0w + ti;
                int i1 = (rb + g + 8) * BA_STR + k0w + ti;
                ah[mt][0] = Ah[i0];
                ah[mt][1] = Ah[i1];
                ah[mt][2] = Ah[i0 + 4];
                ah[mt][3] = Ah[i1 + 4];
                al[mt][0] = Al[i0];
                al[mt][1] = Al[i1];
                al[mt][2] = Al[i0 + 4];
                al[mt][3] = Al[i1 + 4];
            }
#pragma unroll
            for (int nt = 0; nt < 8; nt++) {
                int n = wn * 64 + nt * 8 + g;
                int b0 = n * BB_STR + c * 32 + k0w + ti;
                uint32_t bh[2], bl[2];
                bh[0] = Bh[b0]; bh[1] = Bh[b0 + 4];
                bl[0] = Bl[b0]; bl[1] = Bl[b0 + 4];
#pragma unroll
                for (int mt = 0; mt < 2; mt++) {
                    mma_bf16(acc[mt][nt], ah[mt], bh);
                    mma_bf16(acc[mt][nt], ah[mt], bl);
                    mma_bf16(acc[mt][nt], al[mt], bh);
                }
            }
        }
        __syncthreads();
    }

    // ---- epilogue
#pragma unroll
    for (int mt = 0; mt < 2; mt++) {
#pragma unroll
        for (int h = 0; h < 2; h++) {
            int grow = row0 + wm * 32 + mt * 16 + g + h * 8;
            if (grow >= nrows) continue;
            float* cp = job.C + (size_t)grow * job.ldc + job.coff + wn * 64;
#pragma unroll
            for (int nt = 0; nt < 8; nt++) {
                int col = nt * 8 + 2 * ti;
                float vx = acc[mt][nt][2 * h];
                float vy = acc[mt][nt][2 * h + 1];
                if (job.bias) {
                    vx += job.bias[wn * 64 + col];
                    vy += job.bias[wn * 64 + col + 1];
                }
                *(float2*)(cp + col) = make_float2(vx, vy);
            }
        }
    }
}

// ---------------- scalar GEMM (classifier only, ncols=40) -------------------
struct GemmJob {
    const float* A;
    const float* B;
    const float* bias;
    float*       C;
    int ldc;
    int coff;
    int ncols;
};
struct GemmJobs { GemmJob j[2]; };

__device__ __forceinline__ void fma2(unsigned long long& d,
                                     unsigned long long a, unsigned long long b) {
    asm("fma.rn.f32x2 %0, %1, %2, %0;" : "+l"(d) : "l"(a), "l"(b));
}
__device__ __forceinline__ void unpack2(unsigned long long v, float& lo, float& hi) {
    asm("mov.b64 {%0, %1}, %2;" : "=f"(lo), "=f"(hi) : "l"(v));
}

#define AS_STRIDE 260
#define BS_STRIDE 144

__global__ void __launch_bounds__(256, 2) gemm_nt(
    GemmJobs jobs, int nrows)
{
    const GemmJob job = jobs.j[blockIdx.y];
    const float* __restrict__ A    = job.A;
    const float* __restrict__ B    = job.B;
    const float* __restrict__ bias = job.bias;
    const int ncols = job.ncols;
    const int row0  = blockIdx.x * 128;

    __shared__ float As[16][AS_STRIDE];
    __shared__ float Bs[16][BS_STRIDE];

    const int t  = threadIdx.x;
    const int tx = t & 15;
    const int ty = t >> 4;

    unsigned long long acc[8][4];
#pragma unroll
    for (int y = 0; y < 8; y++)
#pragma unroll
        for (int xp = 0; xp < 4; xp++) acc[y][xp] = 0ULL;

    const int b_base = tx * 8 + ((tx >> 2) << 2);

    for (int k0 = 0; k0 < 128; k0 += 16) {
#pragma unroll
        for (int i = 0; i < 2; i++) {
            int lin = t + i * 256;
            int r   = lin >> 2;
            int kq  = lin & 3;
            float4 v = make_float4(0.f, 0.f, 0.f, 0.f);
            int grow = row0 + r;
            if (grow < nrows)
                v = *(const float4*)(A + (size_t)grow * 128 + k0 + kq * 4);
            *(float2*)&As[kq * 4 + 0][2 * r] = make_float2(v.x, v.x);
            *(float2*)&As[kq * 4 + 1][2 * r] = make_float2(v.y, v.y);
            *(float2*)&As[kq * 4 + 2][2 * r] = make_float2(v.z, v.z);
            *(float2*)&As[kq * 4 + 3][2 * r] = make_float2(v.w, v.w);
        }
#pragma unroll
        for (int i = 0; i < 2; i++) {
            int lin = t + i * 256;
            int j   = lin >> 2;
            int kq  = lin & 3;
            float4 v = make_float4(0.f, 0.f, 0.f, 0.f);
            if (j < ncols)
                v = *(const float4*)(B + (size_t)j * 128 + k0 + kq * 4);
            int pj = j + ((j >> 5) << 2);
            Bs[kq * 4 + 0][pj] = v.x;
            Bs[kq * 4 + 1][pj] = v.y;
            Bs[kq * 4 + 2][pj] = v.z;
            Bs[kq * 4 + 3][pj] = v.w;
        }
        __syncthreads();
#pragma unroll
        for (int kk = 0; kk < 16; kk++) {
            unsigned long long ad[8], bp[4];
            const ulonglong2* ap = (const ulonglong2*)&As[kk][ty * 16];
            const ulonglong2* bq = (const ulonglong2*)&Bs[kk][b_base];
#pragma unroll
            for (int i = 0; i < 4; i++) {
                ulonglong2 u = ap[i];
                ad[2 * i]     = u.x;
                ad[2 * i + 1] = u.y;
            }
#pragma unroll
            for (int i = 0; i < 2; i++) {
                ulonglong2 u = bq[i];
                bp[2 * i]     = u.x;
                bp[2 * i + 1] = u.y;
            }
#pragma unroll
            for (int y = 0; y < 8; y++)
#pragma unroll
                for (int xp = 0; xp < 4; xp++)
                    fma2(acc[y][xp], ad[y], bp[xp]);
        }
        __syncthreads();
    }

#pragma unroll
    for (int y = 0; y < 8; y++) {
        int grow = row0 + ty * 8 + y;
        if (grow >= nrows) continue;
        float* cp = job.C + (size_t)grow * job.ldc + job.coff;
        float c[8];
#pragma unroll
        for (int xp = 0; xp < 4; xp++)
            unpack2(acc[y][xp], c[2 * xp], c[2 * xp + 1]);
#pragma unroll
        for (int xq = 0; xq < 2; xq++) {
            int col = tx * 8 + xq * 4;
            if (col >= ncols) continue;
            float4 v = make_float4(c[xq * 4 + 0], c[xq * 4 + 1],
                                   c[xq * 4 + 2], c[xq * 4 + 3]);
            if (bias) {
                v.x += bias[col + 0];
                v.y += bias[col + 1];
                v.z += bias[col + 2];
                v.w += bias[col + 3];
            }
            *(float4*)(cp + col) = v;
        }
    }
}

// ---------------- BatchNorm --------------------------------------------------
__global__ void bn_stats(const float* __restrict__ X, float* __restrict__ stats)
{
    int c  = threadIdx.x;
    int r0 = blockIdx.x * 64;
    int r1 = min(r0 + 64, N_NODES);
    float s = 0.f, q = 0.f;
    for (int r = r0; r < r1; r++) {
        float v = X[(size_t)r * 128 + c];
        s += v;
        q = fmaf(v, v, q);
    }
    atomicAdd(&stats[c], s);
    atomicAdd(&stats[128 + c], q);
}

__global__ void bn_apply(const float4* __restrict__ X, const float* __restrict__ stats,
                         const float* __restrict__ gamma, const float* __restrict__ beta,
                         const float4* __restrict__ residual, float4* __restrict__ out)
{
    int i = blockIdx.x * blockDim.x + threadIdx.x;
    if (i >= N_NODES * 32) return;
    int c0 = (i & 31) * 4;
    const float invN = 1.f / (float)N_NODES;
    float4 v = X[i];
    float r[4] = {v.x, v.y, v.z, v.w};
#pragma unroll
    for (int k = 0; k < 4; k++) {
        int c = c0 + k;
        float m   = stats[c] * invN;
        float var = stats[128 + c] * invN - m * m;
        float u = gamma[c] * (r[k] - m) * rsqrtf(var + 1e-5f) + beta[c];
        r[k] = fmaxf(u, 0.f);
    }
    float4 o = make_float4(r[0], r[1], r[2], r[3]);
    if (residual) {
        float4 rv = residual[i];
        o.x += rv.x; o.y += rv.y; o.z += rv.z; o.w += rv.w;
    }
    out[i] = o;
}

// ---------------- small utility kernels -------------------------------------
__global__ void zero_f(float* __restrict__ p, int n)
{
    int i = blockIdx.x * blockDim.x + threadIdx.x;
    if (i < n) p[i] = 0.f;
}

__global__ void recip_f(float* __restrict__ p, int n)
{
    int i = blockIdx.x * blockDim.x + threadIdx.x;
    if (i < n) p[i] = 1.f / p[i];
}

__global__ void init_counts_k(int* __restrict__ cnt)
{
    int i = blockIdx.x * blockDim.x + threadIdx.x;
    if (i < N_NODES) cnt[i] = 1;   // self loop
}

__global__ void hist_k(const int* __restrict__ ei1, int* __restrict__ cnt)
{
    int e = blockIdx.x * blockDim.x + threadIdx.x;
    if (e < N_EDGES) atomicAdd(&cnt[ei1[e]], 1);
}

__global__ void scan_k(const int* __restrict__ cnt, int* __restrict__ off,
                       int* __restrict__ cur)
{
    __shared__ int sh[1024];
    const int CH = (N_NODES + 1023) / 1024;
    int t = threadIdx.x;
    int base = t * CH;
    int local = 0;
    for (int i = 0; i < CH; i++) {
        int idx = base + i;
        if (idx < N_NODES) local += cnt[idx];
    }
    sh[t] = local;
    __syncthreads();
    for (int o = 1; o < 1024; o <<= 1) {
        int v = 0;
        if (t >= o) v = sh[t - o];
        __syncthreads();
        if (t >= o) sh[t] += v;
        __syncthreads();
    }
    int run = (t == 0) ? 0 : sh[t - 1];
    for (int i = 0; i < CH; i++) {
        int idx = base + i;
        if (idx < N_NODES) {
            off[idx] = run;
            cur[idx] = run;
            run += cnt[idx];
        }
    }
    if (t == 0) off[N_NODES] = EAUG;
}

__global__ void csr_fill_k(const int* __restrict__ ei1, int* __restrict__ cur,
                           int* __restrict__ eid)
{
    int e = blockIdx.x * blockDim.x + threadIdx.x;
    if (e >= EAUG) return;
    int c = (e < N_EDGES) ? ei1[e] : (e - N_EDGES);
    int pos = atomicAdd(&cur[c], 1);
    eid[pos] = e;
}

// ---------------- per-node Wh dots -------------------------------------------
__global__ void pq_kernel(const float* __restrict__ G, const float* __restrict__ Wh,
                          float2* __restrict__ PQ)
{
    int node = (blockIdx.x * blockDim.x + threadIdx.x) >> 5;
    int lane = threadIdx.x & 31;
    if (node >= N_NODES) return;
    float4 xg = ((const float4*)(G + (size_t)node * 256))[lane];
    float4 a  = ((const float4*)Wh)[lane];
    float4 b  = ((const float4*)Wh)[lane + 32];
    float p = xg.x * a.x + xg.y * a.y + xg.z * a.z + xg.w * a.w;
    float q = xg.x * b.x + xg.y * b.y + xg.z * b.z + xg.w * b.w;
#pragma unroll
    for (int o = 16; o > 0; o >>= 1) {
        p += __shfl_xor_sync(0xffffffffu, p, o);
        q += __shfl_xor_sync(0xffffffffu, q, o);
    }
    if (lane == 0) PQ[node] = make_float2(p, q);
}

// ---------------- edge pass 1: FOUR edges per warp, full 32-lane rows --------
// 8 independent float4 gathers per lane; 4 sums reduce in one butterfly;
// scalar tails run in parallel on lanes 0/8/16/24.
__global__ void edge_pass1(const float* __restrict__ G,
                           const int* __restrict__ ei0, const int* __restrict__ ei1,
                           const float2* __restrict__ PQ, const float* __restrict__ bh,
                           float2* __restrict__ s_buf, float* __restrict__ Z)
{
    int warp = (blockIdx.x * blockDim.x + threadIdx.x) >> 5;
    int lane = threadIdx.x & 31;
    int e0 = 4 * warp;
    if (e0 >= EAUG) return;   // EAUG % 4 == 0; all four edges valid together

    int r[4], c[4];
#pragma unroll
    for (int k = 0; k < 4; k++) {
        int e = e0 + k;
        if (e < N_EDGES) { r[k] = ei0[e]; c[k] = ei1[e]; }
        else             { r[k] = e - N_EDGES; c[k] = r[k]; }
    }

    float ss[4];
#pragma unroll
    for (int k = 0; k < 4; k++) {
        float4 xr = ((const float4*)(G + (size_t)r[k] * 256))[lane];
        float4 xc = ((const float4*)(G + (size_t)c[k] * 256))[lane];
        float dx = xr.x - xc.x, dy = xr.y - xc.y;
        float dz = xr.z - xc.z, dw = xr.w - xc.w;
        ss[k] = dx * dx + dy * dy + dz * dz + dw * dw;
    }
#pragma unroll
    for (int o = 16; o > 0; o >>= 1) {
        ss[0] += __shfl_xor_sync(0xffffffffu, ss[0], o);
        ss[1] += __shfl_xor_sync(0xffffffffu, ss[1], o);
        ss[2] += __shfl_xor_sync(0xffffffffu, ss[2], o);
        ss[3] += __shfl_xor_sync(0xffffffffu, ss[3], o);
    }
    if ((lane & 7) == 0) {
        int k = lane >> 3;                       // 0,1,2,3 for lanes 0,8,16,24
        float sk = ss[k];
        int   e  = e0 + k;
        int   rr = r[k];
        int   cc = c[k];
        float g = sqrtf(sk + 1e-12f);
        float t = PQ[rr].x + PQ[cc].y + bh[0];
        float h = fmaxf(t, 0.f) + log1pf(__expf(-fabsf(t)));   // softplus
        float s = 1.f / (1.f + __expf(g + h));                 // sigmoid(-(g+h))
        float es = __expf(s);
        float ed = __expf(1.f - s);
        s_buf[e] = make_float2(es, ed);
        atomicAdd(&Z[rr],           es);
        atomicAdd(&Z[N_NODES + rr], ed);
    }
}

// ---------------- aggregation of RAW input features -------------------------
__global__ void agg_k(const float* __restrict__ X,
                      const int* __restrict__ off, const int* __restrict__ eid,
                      const int* __restrict__ ei0,
                      const float2* __restrict__ s_buf, const float* __restrict__ invZ,
                      float* __restrict__ SC, float* __restrict__ SD)
{
    int node = (blockIdx.x * blockDim.x + threadIdx.x) >> 5;
    int lane = threadIdx.x & 31;
    if (node >= N_NODES) return;

    int p0 = off[node], p1 = off[node + 1];
    float4 ac = make_float4(0.f, 0.f, 0.f, 0.f);
    float4 ad = make_float4(0.f, 0.f, 0.f, 0.f);
    for (int p = p0; p < p1; p++) {
        int e = eid[p];
        int r = (e < N_EDGES) ? ei0[e] : (e - N_EDGES);
        float2 es = s_buf[e];
        float wc = es.x * invZ[r];
        float wd = es.y * invZ[N_NODES + r];
        float4 v = ((const float4*)(X + (size_t)r * 128))[lane];
        ac.x = fmaf(wc, v.x, ac.x); ac.y = fmaf(wc, v.y, ac.y);
        ac.z = fmaf(wc, v.z, ac.z); ac.w = fmaf(wc, v.w, ac.w);
        ad.x = fmaf(wd, v.x, ad.x); ad.y = fmaf(wd, v.y, ad.y);
        ad.z = fmaf(wd, v.z, ad.z); ad.w = fmaf(wd, v.w, ad.w);
    }
    ((float4*)(SC + (size_t)node * 128))[lane] = ac;
    ((float4*)(SD + (size_t)node * 128))[lane] = ad;
}

// ---------------- gate + combine + residual ----------------------------------
__global__ void gate_k(const float* __restrict__ OC, const float* __restrict__ OD,
                       const float* __restrict__ G,
                       const float* __restrict__ Wgate, const float* __restrict__ bgate,
                       const float* __restrict__ residual, float* __restrict__ out)
{
    int node = (blockIdx.x * blockDim.x + threadIdx.x) >> 5;
    int lane = threadIdx.x & 31;
    if (node >= N_NODES) return;

    float4 ac = ((const float4*)(OC + (size_t)node * 128))[lane];
    float4 ad = ((const float4*)(OD + (size_t)node * 128))[lane];
    float4 sf = ((const float4*)(G + (size_t)node * 256 + 128))[lane];

    float l[3];
#pragma unroll
    for (int k = 0; k < 3; k++) {
        float4 w0 = ((const float4*)(Wgate + k * 384))[lane];
        float4 w1 = ((const float4*)(Wgate + k * 384 + 128))[lane];
        float4 w2 = ((const float4*)(Wgate + k * 384 + 256))[lane];
        l[k] = w0.x * ac.x + w0.y * ac.y + w0.z * ac.z + w0.w * ac.w
             + w1.x * ad.x + w1.y * ad.y + w1.z * ad.z + w1.w * ad.w
             + w2.x * sf.x + w2.y * sf.y + w2.z * sf.z + w2.w * sf.w;
    }
#pragma unroll
    for (int o = 16; o > 0; o >>= 1) {
        l[0] += __shfl_xor_sync(0xffffffffu, l[0], o);
        l[1] += __shfl_xor_sync(0xffffffffu, l[1], o);
        l[2] += __shfl_xor_sync(0xffffffffu, l[2], o);
    }
    l[0] += bgate[0]; l[1] += bgate[1]; l[2] += bgate[2];
    float m  = fmaxf(l[0], fmaxf(l[1], l[2]));
    float e0 = __expf(l[0] - m), e1 = __expf(l[1] - m), e2 = __expf(l[2] - m);
    float inv = 1.f / (e0 + e1 + e2);
    float g0 = e0 * inv, g1 = e1 * inv, g2 = e2 * inv;

    float4 o4;
    o4.x = g0 * ac.x + g1 * ad.x + g2 * sf.x;
    o4.y = g0 * ac.y + g1 * ad.y + g2 * sf.y;
    o4.z = g0 * ac.z + g1 * ad.z + g2 * sf.z;
    o4.w = g0 * ac.w + g1 * ad.w + g2 * sf.w;
    if (residual) {
        float4 rv = ((const float4*)(residual + (size_t)node * 128))[lane];
        o4.x += rv.x; o4.y += rv.y; o4.z += rv.z; o4.w += rv.w;
    }
    ((float4*)(out + (size_t)node * 128))[lane] = o4;
}

// ---------------- launch ------------------------------------------------------
extern "C" void kernel_launch(void* const* d_in, const int* in_sizes, int n_in,
                              void* d_out, int out_size)
{
    (void)in_sizes; (void)n_in; (void)out_size;
    const float* x       = (const float*)d_in[0];
    const int*   ei      = (const int*)d_in[1];
    const float* mlp_W   = (const float*)d_in[2];
    const float* mlp_b   = (const float*)d_in[3];
    const float* mlp_g   = (const float*)d_in[4];
    const float* mlp_be  = (const float*)d_in[5];
    const float* bn0_g   = (const float*)d_in[6];
    const float* bn0_be  = (const float*)d_in[7];
    const float* cls_W   = (const float*)d_in[8];
    const float* cls_b   = (const float*)d_in[9];
    const float* Wg[2]    = {(const float*)d_in[10], (const float*)d_in[19]};
    const float* Wh[2]    = {(const float*)d_in[11], (const float*)d_in[20]};
    const float* bh[2]    = {(const float*)d_in[12], (const float*)d_in[21]};
    const float* Wcon[2]  = {(const float*)d_in[13], (const float*)d_in[22]};
    const float* Wdis[2]  = {(const float*)d_in[14], (const float*)d_in[23]};
    const float* Wself[2] = {(const float*)d_in[15], (const float*)d_in[24]};
    const float* bself[2] = {(const float*)d_in[16], (const float*)d_in[25]};
    const float* Wgate[2] = {(const float*)d_in[17], (const float*)d_in[26]};
    const float* bgate[2] = {(const float*)d_in[18], (const float*)d_in[27]};
    const int* ei0 = ei;
    const int* ei1 = ei + N_EDGES;
    float* out = (float*)d_out;

    float *pH0, *pX1, *pTmp, *pG, *pSC, *pSD, *pZ, *pStats;
    float2 *pS, *pPQ;
    int *pOff, *pCur, *pCnt, *pEid;
    cudaGetSymbolAddress((void**)&pH0,   d_h0);
    cudaGetSymbolAddress((void**)&pX1,   d_x1);
    cudaGetSymbolAddress((void**)&pTmp,  d_tmp);
    cudaGetSymbolAddress((void**)&pG,    d_G);
    cudaGetSymbolAddress((void**)&pSC,   d_SC);
    cudaGetSymbolAddress((void**)&pSD,   d_SD);
    cudaGetSymbolAddress((void**)&pPQ,   d_PQ);
    cudaGetSymbolAddress((void**)&pS,    d_s);
    cudaGetSymbolAddress((void**)&pZ,    d_Z);
    cudaGetSymbolAddress((void**)&pStats,d_stats);
    cudaGetSymbolAddress((void**)&pOff,  d_off);
    cudaGetSymbolAddress((void**)&pCur,  d_cur);
    cudaGetSymbolAddress((void**)&pCnt,  d_cnt);
    cudaGetSymbolAddress((void**)&pEid,  d_eid);

    cudaFuncSetAttribute(gemm_tc, cudaFuncAttributeMaxDynamicSharedMemorySize,
                         BSM_TOTAL);

    const int GR = (N_NODES + 127) / 128;          // 391 row blocks
    const int NODE_WARPS = (N_NODES * 32 + 255) / 256;
    const int EDGE_WARPS = ((EAUG / 4) * 32 + 255) / 256;

    // ---- fork: CSR build (independent of features) runs on side stream
    cudaEventRecord(g_ev[0], 0);
    cudaStreamWaitEvent(g_s1, g_ev[0], 0);
    init_counts_k<<<(N_NODES + 255) / 256, 256, 0, g_s1>>>(pCnt);
    hist_k<<<(N_EDGES + 255) / 256, 256, 0, g_s1>>>(ei1, pCnt);
    scan_k<<<1, 1024, 0, g_s1>>>(pCnt, pOff, pCur);
    csr_fill_k<<<(EAUG + 255) / 256, 256, 0, g_s1>>>(ei1, pCur, pEid);
    cudaEventRecord(g_ev[1], g_s1);

    // ---- MLP + BN + relu -> h0 (main stream, overlaps CSR build)
    {
        TJobs tj = {};
        tj.j[0] = {x, mlp_W, mlp_b, pTmp, 128, 0};
        tj.j[1] = tj.j[0];
        gemm_tc<<<dim3(GR, 1), 256, BSM_TOTAL>>>(tj, N_NODES);
    }
    zero_f<<<1, 256>>>(pStats, 256);
    bn_stats<<<(N_NODES + 63) / 64, 128>>>(pTmp, pStats);
    bn_apply<<<NODE_WARPS, 256>>>((const float4*)pTmp, pStats,
                                  mlp_g, mlp_be, nullptr, (float4*)pH0);

    // ---- conv layers
    const float* lin[2] = {pH0, pX1};
    for (int l = 0; l < 2; l++) {
        const float* X = lin[l];
        // fork: zero Z on side stream (prev consumer of Z already ordered here)
        cudaEventRecord(g_ev[2 + 2 * l], 0);
        cudaStreamWaitEvent(g_s1, g_ev[2 + 2 * l], 0);
        zero_f<<<(2 * N_NODES + 255) / 256, 256, 0, g_s1>>>(pZ, 2 * N_NODES);
        cudaEventRecord(g_ev[3 + 2 * l], g_s1);

        {   // G = [X@Wg.T | X@Wself.T + bself]
            TJobs tj = {};
            tj.j[0] = {X, Wg[l],    nullptr,  pG, 256, 0};
            tj.j[1] = {X, Wself[l], bself[l], pG, 256, 128};
            gemm_tc<<<dim3(GR, 2), 256, BSM_TOTAL>>>(tj, N_NODES);
        }
        pq_kernel<<<NODE_WARPS, 256>>>(pG, Wh[l], pPQ);
        cudaStreamWaitEvent(0, g_ev[3 + 2 * l], 0);   // Z zeroed
        edge_pass1<<<EDGE_WARPS, 256>>>(pG, ei0, ei1, pPQ, bh[l], pS, pZ);
        recip_f<<<(2 * N_NODES + 255) / 256, 256>>>(pZ, 2 * N_NODES);
        if (l == 0)
            cudaStreamWaitEvent(0, g_ev[1], 0);       // CSR ready
        agg_k<<<NODE_WARPS, 256>>>(X, pOff, pEid, ei0, pS, pZ, pSC, pSD);
        {   // SC = SC@Wcon.T, SD = SD@Wdis.T (in place; rows disjoint per CTA)
            TJobs tj = {};
            tj.j[0] = {pSC, Wcon[l], nullptr, pSC, 128, 0};
            tj.j[1] = {pSD, Wdis[l], nullptr, pSD, 128, 0};
            gemm_tc<<<dim3(GR, 2), 256, BSM_TOTAL>>>(tj, N_NODES);
        }
        gate_k<<<NODE_WARPS, 256>>>(pSC, pSD, pG, Wgate[l], bgate[l],
                                    (l == 0) ? nullptr : pX1, pTmp);
        if (l == 0) {
            zero_f<<<1, 256>>>(pStats, 256);
            bn_stats<<<(N_NODES + 63) / 64, 128>>>(pTmp, pStats);
            bn_apply<<<NODE_WARPS, 256>>>((const float4*)pTmp, pStats,
                                          bn0_g, bn0_be,
                                          (const float4*)pH0, (float4*)pX1);
        }
    }

    // ---- classifier: out = x2 @ cls_W.T + cls_b   (x2 lives in d_tmp)
    {
        GemmJobs gj = {};
        gj.j[0] = {pTmp, cls_W, cls_b, out, 40, 0, 40};
        gj.j[1] = gj.j[0];
        gemm_nt<<<dim3(GR, 1), 256>>>(gj, N_NODES);
    }
}